// round 11
// baseline (speedup 1.0000x reference)
#include <cuda_runtime.h>
#include <cuda_fp16.h>
#include <cuda_bf16.h>
#include <cuda.h>
#include <cstdint>

// ---------------- problem dims ----------------
static constexpr int HD   = 4096;
static constexpr int MDIM = 14336;
static constexpr int NTOK = 8192;   // 4 * 2048 tokens

// fp16 scratch (used only when needed) + intermediate h (always fp16)
__device__ __align__(1024) __half g_x16[(size_t)NTOK * HD];
__device__ __align__(1024) __half g_wg16[(size_t)MDIM * HD];
__device__ __align__(1024) __half g_wu16[(size_t)MDIM * HD];
__device__ __align__(1024) __half g_wd16[(size_t)HD * MDIM];
__device__ __align__(1024) __half g_hbuf[(size_t)NTOK * MDIM];
__device__ int g_dtype;   // 0 = fp16, 1 = bf16, 2 = fp32

// ---------------- dtype detector ----------------
__device__ __forceinline__ bool plaus_f(float v) {
    return isfinite(v) && fabsf(v) > 1e-4f && fabsf(v) < 100.0f;
}
__device__ __forceinline__ float h_bits(uint32_t b) {
    __half_raw r; r.x = (unsigned short)b;
    return __half2float(*reinterpret_cast<__half*>(&r));
}
__global__ void detect_dtype_k(const uint32_t* __restrict__ w) {
    __shared__ int c[3];
    if (threadIdx.x < 3) c[threadIdx.x] = 0;
    __syncthreads();
    int c16 = 0, cb = 0, c32 = 0;
    for (int i = threadIdx.x; i < 8192; i += 256) {
        uint32_t v = w[i];
        if (plaus_f(__uint_as_float(v))) c32++;
        uint32_t lo = v & 0xFFFFu, hi = v >> 16;
        if (plaus_f(h_bits(lo)) && plaus_f(h_bits(hi))) c16++;
        if (plaus_f(__uint_as_float(lo << 16)) && plaus_f(__uint_as_float(v & 0xFFFF0000u))) cb++;
    }
    atomicAdd(&c[0], c16); atomicAdd(&c[1], cb); atomicAdd(&c[2], c32);
    __syncthreads();
    if (threadIdx.x == 0) {
        const int thresh = (8192 * 9) / 10;
        int dt;
        if (c[1] > thresh)      dt = 1;
        else if (c[0] > thresh) dt = 0;
        else                    dt = 2;
        g_dtype = dt;
    }
}

// ---------------- conditional conversion -> fp16 ----------------
// mode 0: always convert; mode 2: only if dt==2 (fp32); mode 1: if dt != 0
__device__ __forceinline__ void conv_range(const void* src, __half* dst, size_t n,
                                           int dt, size_t start, size_t stride) {
    for (size_t i = start; i < n; i += stride) {
        uint4 o;
        if (dt == 2) {
            const float4* s = reinterpret_cast<const float4*>((const float*)src + i);
            float4 a = s[0], b = s[1];
            __half2 p0 = __floats2half2_rn(a.x, a.y);
            __half2 p1 = __floats2half2_rn(a.z, a.w);
            __half2 p2 = __floats2half2_rn(b.x, b.y);
            __half2 p3 = __floats2half2_rn(b.z, b.w);
            o = make_uint4(*(uint32_t*)&p0, *(uint32_t*)&p1, *(uint32_t*)&p2, *(uint32_t*)&p3);
        } else if (dt == 1) {
            uint4 s = *reinterpret_cast<const uint4*>((const __nv_bfloat16*)src + i);
            uint32_t ws[4] = {s.x, s.y, s.z, s.w};
            uint32_t po[4];
#pragma unroll
            for (int j = 0; j < 4; j++) {
                float f0 = __uint_as_float(ws[j] << 16);
                float f1 = __uint_as_float(ws[j] & 0xFFFF0000u);
                __half2 p = __floats2half2_rn(f0, f1);
                po[j] = *(uint32_t*)&p;
            }
            o = make_uint4(po[0], po[1], po[2], po[3]);
        } else {
            o = *reinterpret_cast<const uint4*>((const __half*)src + i);
        }
        *reinterpret_cast<uint4*>(dst + i) = o;
    }
}
__global__ void convert_to_half_k(const void* __restrict__ src, __half* __restrict__ dst,
                                  size_t n, int mode) {
    const int dt = g_dtype;
    if (mode == 2 && dt != 2) return;
    if (mode == 1 && dt == 0) return;
    const size_t stride = (size_t)gridDim.x * blockDim.x * 8;
    conv_range(src, dst, n, dt, ((size_t)blockIdx.x * blockDim.x + threadIdx.x) * 8, stride);
}
__global__ void convert2_to_half_k(const void* __restrict__ s0, __half* __restrict__ d0,
                                   const void* __restrict__ s1, __half* __restrict__ d1,
                                   size_t n, int mode) {
    const int dt = g_dtype;
    if (mode == 2 && dt != 2) return;
    if (mode == 1 && dt == 0) return;
    const size_t stride = (size_t)gridDim.x * blockDim.x * 8;
    const size_t start = ((size_t)blockIdx.x * blockDim.x + threadIdx.x) * 8;
    conv_range(s0, d0, n, dt, start, stride);
    conv_range(s1, d1, n, dt, start, stride);
}

// ---------------- asm helpers ----------------
__device__ __forceinline__ uint32_t smem_u32(const void* p) {
    uint32_t a;
    asm("{ .reg .u64 t; cvta.to.shared.u64 t, %1; cvt.u32.u64 %0, t; }" : "=r"(a) : "l"(p));
    return a;
}

#define CP_ASYNC16(smem_addr, gptr) \
    asm volatile("cp.async.cg.shared.global [%0], [%1], 16;" \
                 :: "r"(smem_addr), "l"(gptr) : "memory")
#define CP_COMMIT() asm volatile("cp.async.commit_group;" ::: "memory")
#define CP_WAIT(n)  asm volatile("cp.async.wait_group %0;" :: "n"(n) : "memory")
#define CP_WAIT_ALL() asm volatile("cp.async.wait_all;" ::: "memory")

#define MBARRIER_INIT(addr, cnt) \
    asm volatile("mbarrier.init.shared.b64 [%0], %1;" :: "r"((uint32_t)(addr)), "r"((uint32_t)(cnt)) : "memory")
#define MBARRIER_ARRIVE(addr) \
    asm volatile("mbarrier.arrive.shared.b64 _, [%0];" :: "r"((uint32_t)(addr)) : "memory")
#define MBARRIER_EXPECT_TX(addr, bytes) \
    asm volatile("mbarrier.arrive.expect_tx.shared.b64 _, [%0], %1;" :: "r"((uint32_t)(addr)), "r"((uint32_t)(bytes)) : "memory")

#define MBARRIER_WAIT_PARITY(mbar_smem_addr, phase_parity) do { \
    uint32_t _mbar = (uint32_t)(mbar_smem_addr); \
    uint32_t _parity = (uint32_t)(phase_parity); \
    uint32_t _done; \
    asm volatile( \
        "{\n\t.reg .pred p;\n\t" \
        "mbarrier.try_wait.parity.shared.b64 p, [%1], %2;\n\t" \
        "selp.b32 %0, 1, 0, p;\n\t}" \
        : "=r"(_done) : "r"(_mbar), "r"(_parity) : "memory"); \
    if (!_done) { \
        asm volatile( \
            "{\n\t.reg .pred P1;\n\t" \
            "WAIT_LOOP_%=:\n\t" \
            "mbarrier.try_wait.parity.shared.b64 P1, [%0], %1, 0x989680;\n\t" \
            "@P1 bra.uni WAIT_DONE_%=;\n\t" \
            "bra.uni WAIT_LOOP_%=;\n\t" \
            "WAIT_DONE_%=:\n\t}" \
            :: "r"(_mbar), "r"(_parity) : "memory"); \
    } \
} while(0)

#define FENCE_PROXY_ASYNC() \
    asm volatile("fence.proxy.async.shared::cta;" ::: "memory")

__device__ __forceinline__ void tma_load_2d(uint32_t smem_addr, const void* tmap,
                                            int32_t cx, int32_t cy, uint32_t mbar) {
    asm volatile(
        "cp.async.bulk.tensor.2d.shared::cta.global.tile.mbarrier::complete_tx::bytes "
        "[%0], [%1, {%2, %3}], [%4];"
        :: "r"(smem_addr), "l"(tmap), "r"(cx), "r"(cy), "r"(mbar) : "memory");
}

__device__ __forceinline__ void ldsm_x4(uint32_t& r0, uint32_t& r1, uint32_t& r2, uint32_t& r3,
                                        uint32_t addr) {
    asm volatile("ldmatrix.sync.aligned.m8n8.x4.shared.b16 {%0,%1,%2,%3}, [%4];"
                 : "=r"(r0), "=r"(r1), "=r"(r2), "=r"(r3) : "r"(addr));
}

template<bool BF16>
__device__ __forceinline__ void mma_any(float* c, const uint32_t* a, const uint32_t* b) {
    if (BF16)
        asm volatile(
            "mma.sync.aligned.m16n8k16.row.col.f32.bf16.bf16.f32 "
            "{%0,%1,%2,%3}, {%4,%5,%6,%7}, {%8,%9}, {%0,%1,%2,%3};"
            : "+f"(c[0]), "+f"(c[1]), "+f"(c[2]), "+f"(c[3])
            : "r"(a[0]), "r"(a[1]), "r"(a[2]), "r"(a[3]), "r"(b[0]), "r"(b[1]));
    else
        asm volatile(
            "mma.sync.aligned.m16n8k16.row.col.f32.f16.f16.f32 "
            "{%0,%1,%2,%3}, {%4,%5,%6,%7}, {%8,%9}, {%0,%1,%2,%3};"
            : "+f"(c[0]), "+f"(c[1]), "+f"(c[2]), "+f"(c[3])
            : "r"(a[0]), "r"(a[1]), "r"(a[2]), "r"(a[3]), "r"(b[0]), "r"(b[1]));
}

__device__ __forceinline__ void store_out_dtype(void* outv, size_t i0, size_t i1,
                                                const float* a4, int dt) {
    if (dt == 2) {
        *reinterpret_cast<float2*>((float*)outv + i0) = make_float2(a4[0], a4[1]);
        *reinterpret_cast<float2*>((float*)outv + i1) = make_float2(a4[2], a4[3]);
    } else if (dt == 1) {
        __nv_bfloat162 b0 = __floats2bfloat162_rn(a4[0], a4[1]);
        __nv_bfloat162 b1 = __floats2bfloat162_rn(a4[2], a4[3]);
        *reinterpret_cast<__nv_bfloat162*>((__nv_bfloat16*)outv + i0) = b0;
        *reinterpret_cast<__nv_bfloat162*>((__nv_bfloat16*)outv + i1) = b1;
    } else {
        *reinterpret_cast<__half2*>((__half*)outv + i0) = __floats2half2_rn(a4[0], a4[1]);
        *reinterpret_cast<__half2*>((__half*)outv + i1) = __floats2half2_rn(a4[2], a4[3]);
    }
}

// consumer mainloop (proven structure, f32-accum), templated on element type
template<bool BF16, int KITERS, int NSTAGES>
__device__ __forceinline__ void consumer_loop(
    uint32_t sb, uint32_t off_full, uint32_t off_empty, uint32_t off_tile,
    uint32_t stage_bytes, uint32_t boff,
    uint32_t a_row, uint32_t a_koff, uint32_t b_row, uint32_t b_koff, uint32_t xor7,
    int lane, float (&acc)[4][4][4])
{
    int s = 0, ph = 0;
    for (int k = 0; k < KITERS; k++) {
        MBARRIER_WAIT_PARITY(sb + off_full + s * 8, ph);
        const uint32_t stA = sb + off_tile + (uint32_t)s * stage_bytes;
        const uint32_t stB = stA + boff;
#pragma unroll
        for (int ks = 0; ks < 4; ks++) {
            const uint32_t kbA = ((uint32_t)(ks * 32) + a_koff) ^ xor7;
            const uint32_t kbB = ((uint32_t)(ks * 32) + b_koff) ^ xor7;
            uint32_t aF[4][4];
#pragma unroll
            for (int mb = 0; mb < 4; mb++)
                ldsm_x4(aF[mb][0], aF[mb][1], aF[mb][2], aF[mb][3],
                        stA + (a_row + mb * 16) * 128 + kbA);
            uint32_t bF[2][4];
#pragma unroll
            for (int nb = 0; nb < 2; nb++)
                ldsm_x4(bF[nb][0], bF[nb][1], bF[nb][2], bF[nb][3],
                        stB + (b_row + nb * 16) * 128 + kbB);
#pragma unroll
            for (int mb = 0; mb < 4; mb++)
#pragma unroll
                for (int ns = 0; ns < 4; ns++)
                    mma_any<BF16>(acc[mb][ns], aF[mb], &bF[ns >> 1][(ns & 1) * 2]);
        }
        if (lane == 0) MBARRIER_ARRIVE(sb + off_empty + s * 8);
        if (++s == NSTAGES) { s = 0; ph ^= 1; }
    }
}

// =======================================================================
// TMA GEMM (proven config: 16 compute warps 64x32 + producer = 544 thr).
// FUSED  (MTILE=128): warps 0-7 gate, 8-15 up, shared A; silu-combine -> fp16 h.
//        Epilogue 'up' exchange packed as half2 (32 KB).
// !FUSED (MTILE=256): 4x4 warp grid; store in detected dtype.
// =======================================================================
template<int MTILE, int NSTAGES, bool FUSED, int NTM, int GRP>
__global__ void __launch_bounds__(544, 1)
mlp_gemm_tma(const __grid_constant__ CUtensorMap mapAo,
             const __grid_constant__ CUtensorMap mapAc,
             const __grid_constant__ CUtensorMap mapB0o,
             const __grid_constant__ CUtensorMap mapB0c,
             const __grid_constant__ CUtensorMap mapB1o,
             const __grid_constant__ CUtensorMap mapB1c,
             void* __restrict__ outv)
{
    constexpr int KDIM       = FUSED ? HD : MDIM;
    constexpr int KITERS     = KDIM / 64;
    constexpr int OUT_STRIDE = FUSED ? MDIM : HD;
    constexpr uint32_t ATILE = (uint32_t)MTILE * 128;
    constexpr uint32_t BTILE = 128 * 128;
    constexpr uint32_t STAGE = ATILE + (FUSED ? 2 : 1) * BTILE;

    extern __shared__ char smem_raw[];
    const uint32_t raw = smem_u32(smem_raw);
    const uint32_t sb  = (raw + 1023u) & ~1023u;

    const int tid  = threadIdx.x;
    const int wid  = tid >> 5;
    const int lane = tid & 31;
    const int dt   = g_dtype;

    const uint32_t OFF_FULL  = 0;
    const uint32_t OFF_EMPTY = 256;
    const uint32_t OFF_TILE  = 1024;

    if (tid == 0) {
        for (int s = 0; s < NSTAGES; s++) {
            MBARRIER_INIT(sb + OFF_FULL  + s * 8, 1);
            MBARRIER_INIT(sb + OFF_EMPTY + s * 8, 16);
        }
        FENCE_PROXY_ASYNC();
    }
    __syncthreads();

    // swizzled rasterization: groups of GRP N-tiles x all NTM M-tiles
    const int id = blockIdx.y * gridDim.x + blockIdx.x;
    const int gper = NTM * GRP;
    const int grp = id / gper;
    const int rem = id % gper;
    const int m0 = (rem % NTM) * MTILE;
    const int n0 = (grp * GRP + rem / NTM) * 128;

    // map selection (uniform): A conv only for fp32; B conv for fp32 (FUSED) or dt!=0 (!FUSED)
    const void* pA  = (FUSED && dt == 2) ? (const void*)&mapAc  : (const void*)&mapAo;
    const bool bconv = FUSED ? (dt == 2) : (dt != 0);
    const void* pB0 = bconv ? (const void*)&mapB0c : (const void*)&mapB0o;
    const void* pB1 = bconv ? (const void*)&mapB1c : (const void*)&mapB1o;

    if (wid == 16) {
        // ---------------- TMA producer ----------------
        if (lane == 0) {
            int s = 0, ph = 1;
            for (int k = 0; k < KITERS; k++) {
                MBARRIER_WAIT_PARITY(sb + OFF_EMPTY + s * 8, ph);
                MBARRIER_EXPECT_TX(sb + OFF_FULL + s * 8, STAGE);
                const uint32_t st = sb + OFF_TILE + (uint32_t)s * STAGE;
                tma_load_2d(st,         pA,  k * 64, m0, sb + OFF_FULL + s * 8);
                tma_load_2d(st + ATILE, pB0, k * 64, n0, sb + OFF_FULL + s * 8);
                if (FUSED)
                    tma_load_2d(st + ATILE + BTILE, pB1, k * 64, n0, sb + OFF_FULL + s * 8);
                if (++s == NSTAGES) { s = 0; ph ^= 1; }
            }
        }
    } else {
        // ---------------- compute warps (64x32 tiles, proven layout) ----------------
        const int  cq    = FUSED ? (wid & 7) : wid;
        const bool is_up = FUSED && (wid >= 8);
        const int  wm0   = FUSED ? (cq & 1) * 64 : (cq & 3) * 64;
        const int  wn0   = FUSED ? (cq >> 1) * 32 : (cq >> 2) * 32;

        const uint32_t xor7   = (uint32_t)(lane & 7) << 4;
        const uint32_t a_row  = (uint32_t)(wm0 + (lane & 15));
        const uint32_t a_koff = (uint32_t)(lane & 16);
        const uint32_t b_row  = (uint32_t)(wn0 + (lane & 7) + ((lane & 16) >> 1));
        const uint32_t b_koff = (uint32_t)((lane & 8) << 1);
        const uint32_t boff   = ATILE + (is_up ? BTILE : 0);

        float acc[4][4][4];
#pragma unroll
        for (int i = 0; i < 4; i++)
#pragma unroll
            for (int j = 0; j < 4; j++)
#pragma unroll
                for (int v = 0; v < 4; v++) acc[i][j][v] = 0.0f;

        if (FUSED && dt == 1)
            consumer_loop<true,  KITERS, NSTAGES>(sb, OFF_FULL, OFF_EMPTY, OFF_TILE, STAGE,
                                                  boff, a_row, a_koff, b_row, b_koff, xor7,
                                                  lane, acc);
        else
            consumer_loop<false, KITERS, NSTAGES>(sb, OFF_FULL, OFF_EMPTY, OFF_TILE, STAGE,
                                                  boff, a_row, a_koff, b_row, b_koff, xor7,
                                                  lane, acc);

        const int g = lane >> 2, c2 = (lane & 3) * 2;

        if (!FUSED) {
#pragma unroll
            for (int mb = 0; mb < 4; mb++)
#pragma unroll
                for (int ns = 0; ns < 4; ns++) {
                    const int mrow = m0 + wm0 + mb * 16 + g;
                    const int ncol = n0 + wn0 + ns * 8 + c2;
                    store_out_dtype(outv, (size_t)mrow * OUT_STRIDE + ncol,
                                    (size_t)(mrow + 8) * OUT_STRIDE + ncol,
                                    acc[mb][ns], dt);
                }
            return;
        }

        // fused epilogue: exchange 'up' via SMEM as packed half2, silu-combine
        __syncthreads();   // (1)
        uint32_t* exch = reinterpret_cast<uint32_t*>(smem_raw + (sb - raw) + OFF_TILE);
        __half* out = reinterpret_cast<__half*>(outv);
        if (is_up) {
            const int t = (wid - 8) * 32 + lane;   // 0..255
#pragma unroll
            for (int mb = 0; mb < 4; mb++)
#pragma unroll
                for (int ns = 0; ns < 4; ns++) {
                    __half2 p0 = __floats2half2_rn(acc[mb][ns][0], acc[mb][ns][1]);
                    __half2 p1 = __floats2half2_rn(acc[mb][ns][2], acc[mb][ns][3]);
                    exch[((mb * 4 + ns) * 2 + 0) * 256 + t] = *reinterpret_cast<uint32_t*>(&p0);
                    exch[((mb * 4 + ns) * 2 + 1) * 256 + t] = *reinterpret_cast<uint32_t*>(&p1);
                }
        }
        __syncthreads();   // (2)
        if (!is_up) {
            const int t = wid * 32 + lane;
#pragma unroll
            for (int mb = 0; mb < 4; mb++)
#pragma unroll
                for (int ns = 0; ns < 4; ns++) {
                    uint32_t u0 = exch[((mb * 4 + ns) * 2 + 0) * 256 + t];
                    uint32_t u1 = exch[((mb * 4 + ns) * 2 + 1) * 256 + t];
                    const float2 up01 = __half22float2(*reinterpret_cast<__half2*>(&u0));
                    const float2 up23 = __half22float2(*reinterpret_cast<__half2*>(&u1));
                    const float upv[4] = {up01.x, up01.y, up23.x, up23.y};
                    float r[4];
#pragma unroll
                    for (int v = 0; v < 4; v++) {
                        const float gt = acc[mb][ns][v];
                        r[v] = upv[v] * (gt / (1.0f + __expf(-gt)));
                    }
                    const int mrow = m0 + wm0 + mb * 16 + g;
                    const int ncol = n0 + wn0 + ns * 8 + c2;
                    *reinterpret_cast<__half2*>(out + (size_t)mrow * OUT_STRIDE + ncol) =
                        __floats2half2_rn(r[0], r[1]);
                    *reinterpret_cast<__half2*>(out + (size_t)(mrow + 8) * OUT_STRIDE + ncol) =
                        __floats2half2_rn(r[2], r[3]);
                }
        }
        return;
    }

    if (FUSED) { __syncthreads(); __syncthreads(); }
}

// =======================================================================
// Fallback: cp.async GEMM (proven R4) — only if tensormap creation fails
// =======================================================================
template<int NTHREADS>
__device__ __forceinline__ void load_tile(uint32_t smem_tile, const __half* g,
                                          int row0, int kbyte, int ld_elems, int tid) {
    const char* gbase = reinterpret_cast<const char*>(g) + (size_t)row0 * (ld_elems * 2) + kbyte;
#pragma unroll
    for (int c = tid; c < 1024; c += NTHREADS) {
        const int row = c >> 3;
        const int col = (c & 7) << 4;
        const char* src = gbase + (size_t)row * (ld_elems * 2) + col;
        const uint32_t dst = smem_tile + row * 128 + (col ^ ((row & 7) << 4));
        CP_ASYNC16(dst, src);
    }
}

template<int NW, int NSTAGES, bool FUSED>
__global__ void __launch_bounds__(NW * 32, 1)
mlp_gemm_cp(const __half* __restrict__ A, const __half* __restrict__ B0,
            const __half* __restrict__ B1, void* __restrict__ outv)
{
    constexpr int NTH        = NW * 32;
    constexpr int KDIM       = FUSED ? HD : MDIM;
    constexpr int KITERS     = KDIM / 64;
    constexpr int OUT_STRIDE = FUSED ? MDIM : HD;
    constexpr uint32_t ATILE = 128 * 128;
    constexpr uint32_t STAGE = FUSED ? 3 * ATILE : 2 * ATILE;

    extern __shared__ char smem_raw[];
    const uint32_t raw = smem_u32(smem_raw);
    const uint32_t sb  = (raw + 127u) & ~127u;

    const int tid  = threadIdx.x;
    const int wid  = tid >> 5;
    const int lane = tid & 31;

    const int m0 = blockIdx.x * 128;
    const int n0 = blockIdx.y * 128;

    const int  cq    = FUSED ? (wid & 7) : wid;
    const bool is_up = FUSED && (wid >= 8);
    const int  wm0   = (cq & 1) * 64;
    const int  wn0   = (cq >> 1) * 32;

    const uint32_t xor7   = (uint32_t)(lane & 7) << 4;
    const uint32_t a_row  = (uint32_t)(wm0 + (lane & 15));
    const uint32_t a_koff = (uint32_t)(lane & 16);
    const uint32_t b_row  = (uint32_t)(wn0 + (lane & 7) + ((lane & 16) >> 1));
    const uint32_t b_koff = (uint32_t)((lane & 8) << 1);
    const uint32_t boff   = is_up ? 2 * ATILE : ATILE;

    float acc[4][4][4];
#pragma unroll
    for (int i = 0; i < 4; i++)
#pragma unroll
        for (int j = 0; j < 4; j++)
#pragma unroll
            for (int v = 0; v < 4; v++) acc[i][j][v] = 0.0f;

    auto load_stage = [&](int s, int k) {
        const uint32_t st = sb + (uint32_t)s * STAGE;
        const int kb = k * 128;
        load_tile<NTH>(st,         A,  m0, kb, KDIM, tid);
        load_tile<NTH>(st + ATILE, B0, n0, kb, KDIM, tid);
        if (FUSED)
            load_tile<NTH>(st + 2 * ATILE, B1, n0, kb, KDIM, tid);
    };

#pragma unroll
    for (int s = 0; s < NSTAGES - 1; s++) { load_stage(s, s); CP_COMMIT(); }

    int sc = 0;
    for (int k = 0; k < KITERS; k++) {
        CP_WAIT(NSTAGES - 2);
        __syncthreads();
        const uint32_t stA = sb + (uint32_t)sc * STAGE;
        const uint32_t stB = stA + boff;
#pragma unroll
        for (int ks = 0; ks < 4; ks++) {
            const uint32_t kbA = ((uint32_t)(ks * 32) + a_koff) ^ xor7;
            const uint32_t kbB = ((uint32_t)(ks * 32) + b_koff) ^ xor7;
            uint32_t aF[4][4];
#pragma unroll
            for (int mb = 0; mb < 4; mb++)
                ldsm_x4(aF[mb][0], aF[mb][1], aF[mb][2], aF[mb][3],
                        stA + (a_row + mb * 16) * 128 + kbA);
            uint32_t bF[2][4];
#pragma unroll
            for (int nb = 0; nb < 2; nb++)
                ldsm_x4(bF[nb][0], bF[nb][1], bF[nb][2], bF[nb][3],
                        stB + (b_row + nb * 16) * 128 + kbB);
#pragma unroll
            for (int mb = 0; mb < 4; mb++)
#pragma unroll
                for (int ns = 0; ns < 4; ns++)
                    mma_any<false>(acc[mb][ns], aF[mb], &bF[ns >> 1][(ns & 1) * 2]);
        }
        __syncthreads();
        const int kn = k + NSTAGES - 1;
        if (kn < KITERS) load_stage((sc + NSTAGES - 1) % NSTAGES, kn);
        CP_COMMIT();
        sc = (sc + 1 == NSTAGES) ? 0 : sc + 1;
    }

    const int g = lane >> 2, c2 = (lane & 3) * 2;

    if (!FUSED) {
        const int dt = g_dtype;
#pragma unroll
        for (int mb = 0; mb < 4; mb++)
#pragma unroll
            for (int ns = 0; ns < 4; ns++) {
                const int mrow = m0 + wm0 + mb * 16 + g;
                const int ncol = n0 + wn0 + ns * 8 + c2;
                store_out_dtype(outv, (size_t)mrow * OUT_STRIDE + ncol,
                                (size_t)(mrow + 8) * OUT_STRIDE + ncol, acc[mb][ns], dt);
            }
        return;
    }

    CP_WAIT_ALL();
    __syncthreads();
    float* exch = reinterpret_cast<float*>(smem_raw + (sb - raw));
    __half* out = reinterpret_cast<__half*>(outv);
    if (is_up) {
        const int t = (wid - 8) * 32 + lane;
#pragma unroll
        for (int mb = 0; mb < 4; mb++)
#pragma unroll
            for (int ns = 0; ns < 4; ns++)
#pragma unroll
                for (int v = 0; v < 4; v++)
                    exch[((mb * 4 + ns) * 4 + v) * 256 + t] = acc[mb][ns][v];
    }
    __syncthreads();
    if (!is_up) {
        const int t = wid * 32 + lane;
#pragma unroll
        for (int mb = 0; mb < 4; mb++)
#pragma unroll
            for (int ns = 0; ns < 4; ns++) {
                float r[4];
#pragma unroll
                for (int v = 0; v < 4; v++) {
                    const float gt = acc[mb][ns][v];
                    const float up = exch[((mb * 4 + ns) * 4 + v) * 256 + t];
                    r[v] = up * (gt / (1.0f + __expf(-gt)));
                }
                const int mrow = m0 + wm0 + mb * 16 + g;
                const int ncol = n0 + wn0 + ns * 8 + c2;
                *reinterpret_cast<__half2*>(out + (size_t)mrow * OUT_STRIDE + ncol) =
                    __floats2half2_rn(r[0], r[1]);
                *reinterpret_cast<__half2*>(out + (size_t)(mrow + 8) * OUT_STRIDE + ncol) =
                    __floats2half2_rn(r[2], r[3]);
            }
    }
}

// ---------------- host side ----------------
typedef CUresult (*tmap_encode_fn)(
    CUtensorMap*, CUtensorMapDataType, cuuint32_t, void*,
    const cuuint64_t*, const cuuint64_t*, const cuuint32_t*, const cuuint32_t*,
    CUtensorMapInterleave, CUtensorMapSwizzle, CUtensorMapL2promotion, CUtensorMapFloatOOBfill);

static tmap_encode_fn get_encode_fn() {
    void* fn = nullptr;
    cudaDriverEntryPointQueryResult st;
    if (cudaGetDriverEntryPointByVersion("cuTensorMapEncodeTiled", &fn, 12000,
                                         cudaEnableDefault, &st) == cudaSuccess && fn)
        return (tmap_encode_fn)fn;
    fn = nullptr;
    if (cudaGetDriverEntryPointByVersion("cuTensorMapEncodeTiled", &fn, 13000,
                                         cudaEnableDefault, &st) == cudaSuccess && fn)
        return (tmap_encode_fn)fn;
    return nullptr;
}

static CUresult build_map(tmap_encode_fn enc, CUtensorMap* m, const void* base,
                          uint64_t inner, uint64_t outer, uint32_t box_rows) {
    cuuint64_t dims[2]    = {inner, outer};
    cuuint64_t strides[1] = {inner * 2};
    cuuint32_t box[2]     = {64u, box_rows};
    cuuint32_t es[2]      = {1u, 1u};
    return enc(m, CU_TENSOR_MAP_DATA_TYPE_FLOAT16, 2, const_cast<void*>(base),
               dims, strides, box, es,
               CU_TENSOR_MAP_INTERLEAVE_NONE, CU_TENSOR_MAP_SWIZZLE_128B,
               CU_TENSOR_MAP_L2_PROMOTION_L2_128B, CU_TENSOR_MAP_FLOAT_OOB_FILL_NONE);
}

extern "C" void kernel_launch(void* const* d_in, const int* in_sizes, int n_in,
                              void* d_out, int out_size) {
    (void)in_sizes; (void)n_in; (void)out_size;

    const void* x  = d_in[0];
    const void* wg = d_in[1];
    const void* wu = d_in[2];
    const void* wd = d_in[3];

    void *px, *pwg, *pwu, *pwd, *ph;
    cudaGetSymbolAddress(&px,  g_x16);
    cudaGetSymbolAddress(&pwg, g_wg16);
    cudaGetSymbolAddress(&pwu, g_wu16);
    cudaGetSymbolAddress(&pwd, g_wd16);
    cudaGetSymbolAddress(&ph,  g_hbuf);

    detect_dtype_k<<<1, 256>>>((const uint32_t*)x);
    const size_t nx = (size_t)NTOK * HD, nw = (size_t)MDIM * HD;

    // try TMA path
    bool tma_ok = false;
    CUtensorMap mXo, mXc, mWgo, mWgc, mWuo, mWuc, mWdo, mWdc, mH;
    tmap_encode_fn enc = get_encode_fn();
    if (enc) {
        CUresult r;
        tma_ok = true;
        r = build_map(enc, &mXo,  x,   HD,   NTOK, 128); tma_ok &= (r == CUDA_SUCCESS);
        r = build_map(enc, &mXc,  px,  HD,   NTOK, 128); tma_ok &= (r == CUDA_SUCCESS);
        r = build_map(enc, &mWgo, wg,  HD,   MDIM, 128); tma_ok &= (r == CUDA_SUCCESS);
        r = build_map(enc, &mWgc, pwg, HD,   MDIM, 128); tma_ok &= (r == CUDA_SUCCESS);
        r = build_map(enc, &mWuo, wu,  HD,   MDIM, 128); tma_ok &= (r == CUDA_SUCCESS);
        r = build_map(enc, &mWuc, pwu, HD,   MDIM, 128); tma_ok &= (r == CUDA_SUCCESS);
        r = build_map(enc, &mWdo, wd,  MDIM, HD,   128); tma_ok &= (r == CUDA_SUCCESS);
        r = build_map(enc, &mWdc, pwd, MDIM, HD,   128); tma_ok &= (r == CUDA_SUCCESS);
        r = build_map(enc, &mH,   ph,  MDIM, NTOK, 256); tma_ok &= (r == CUDA_SUCCESS);
    }

    if (tma_ok) {
        // conditional conversions: x/wg/wu only if fp32; wd if not already fp16
        convert_to_half_k<<<(int)(nx / 2048), 256>>>(x, (__half*)px, nx, 2);
        convert2_to_half_k<<<(int)(nw / 2048), 256>>>(wg, (__half*)pwg, wu, (__half*)pwu, nw, 2);
        convert_to_half_k<<<(int)(nw / 2048), 256>>>(wd, (__half*)pwd, nw, 1);

        constexpr int SMEM1 = 2048 + 4 * 48 * 1024;
        constexpr int SMEM2 = 2048 + 4 * 48 * 1024;
        cudaFuncSetAttribute((const void*)mlp_gemm_tma<128, 4, true, 64, 4>,
                             cudaFuncAttributeMaxDynamicSharedMemorySize, SMEM1);
        cudaFuncSetAttribute((const void*)mlp_gemm_tma<256, 4, false, 32, 4>,
                             cudaFuncAttributeMaxDynamicSharedMemorySize, SMEM2);

        mlp_gemm_tma<128, 4, true, 64, 4><<<dim3(NTOK / 128, MDIM / 128), 544, SMEM1>>>(
            mXo, mXc, mWgo, mWgc, mWuo, mWuc, ph);
        mlp_gemm_tma<256, 4, false, 32, 4><<<dim3(NTOK / 256, HD / 128), 544, SMEM2>>>(
            mH, mH, mWdo, mWdc, mWdo, mWdc, d_out);
    } else {
        // fallback: full conversion + proven cp.async kernels
        convert_to_half_k<<<(int)(nx / 2048), 256>>>(x, (__half*)px, nx, 0);
        convert2_to_half_k<<<(int)(nw / 2048), 256>>>(wg, (__half*)pwg, wu, (__half*)pwu, nw, 0);
        convert_to_half_k<<<(int)(nw / 2048), 256>>>(wd, (__half*)pwd, nw, 0);

        constexpr int SMEM1 = 4 * (3 * 128 * 128) + 256;
        constexpr int SMEM2 = 5 * (2 * 128 * 128) + 256;
        cudaFuncSetAttribute((const void*)mlp_gemm_cp<16, 4, true>,
                             cudaFuncAttributeMaxDynamicSharedMemorySize, SMEM1);
        cudaFuncSetAttribute((const void*)mlp_gemm_cp<8, 5, false>,
                             cudaFuncAttributeMaxDynamicSharedMemorySize, SMEM2);

        mlp_gemm_cp<16, 4, true><<<dim3(NTOK / 128, MDIM / 128), 512, SMEM1>>>(
            (__half*)px, (__half*)pwg, (__half*)pwu, ph);
        mlp_gemm_cp<8, 5, false><<<dim3(NTOK / 128, HD / 128), 256, SMEM2>>>(
            (__half*)ph, (__half*)pwd, (__half*)pwd, d_out);
    }
}

// round 14
// speedup vs baseline: 1.0013x; 1.0013x over previous
#include <cuda_runtime.h>
#include <cuda_fp16.h>
#include <cuda_bf16.h>
#include <cuda.h>
#include <cstdint>

// ---------------- problem dims ----------------
static constexpr int HD   = 4096;
static constexpr int MDIM = 14336;
static constexpr int NTOK = 8192;   // 4 * 2048 tokens

// fp16 scratch (used only when needed) + intermediate h (always fp16)
__device__ __align__(1024) __half g_x16[(size_t)NTOK * HD];
__device__ __align__(1024) __half g_wg16[(size_t)MDIM * HD];
__device__ __align__(1024) __half g_wu16[(size_t)MDIM * HD];
__device__ __align__(1024) __half g_wd16[(size_t)HD * MDIM];
__device__ __align__(1024) __half g_hbuf[(size_t)NTOK * MDIM];
__device__ int g_dtype;   // 0 = fp16, 1 = bf16, 2 = fp32

// ---------------- dtype detector ----------------
__device__ __forceinline__ bool plaus_f(float v) {
    return isfinite(v) && fabsf(v) > 1e-4f && fabsf(v) < 100.0f;
}
__device__ __forceinline__ float h_bits(uint32_t b) {
    __half_raw r; r.x = (unsigned short)b;
    return __half2float(*reinterpret_cast<__half*>(&r));
}
__global__ void detect_dtype_k(const uint32_t* __restrict__ w) {
    __shared__ int c[3];
    if (threadIdx.x < 3) c[threadIdx.x] = 0;
    __syncthreads();
    int c16 = 0, cb = 0, c32 = 0;
    for (int i = threadIdx.x; i < 8192; i += 256) {
        uint32_t v = w[i];
        if (plaus_f(__uint_as_float(v))) c32++;
        uint32_t lo = v & 0xFFFFu, hi = v >> 16;
        if (plaus_f(h_bits(lo)) && plaus_f(h_bits(hi))) c16++;
        if (plaus_f(__uint_as_float(lo << 16)) && plaus_f(__uint_as_float(v & 0xFFFF0000u))) cb++;
    }
    atomicAdd(&c[0], c16); atomicAdd(&c[1], cb); atomicAdd(&c[2], c32);
    __syncthreads();
    if (threadIdx.x == 0) {
        const int thresh = (8192 * 9) / 10;
        int dt;
        if (c[1] > thresh)      dt = 1;
        else if (c[0] > thresh) dt = 0;
        else                    dt = 2;
        g_dtype = dt;
    }
}

// ---------------- conditional conversion -> fp16 ----------------
// mode 0: always convert; mode 2: only if dt==2 (fp32); mode 1: if dt != 0
__device__ __forceinline__ void conv_range(const void* src, __half* dst, size_t n,
                                           int dt, size_t start, size_t stride) {
    for (size_t i = start; i < n; i += stride) {
        uint4 o;
        if (dt == 2) {
            const float4* s = reinterpret_cast<const float4*>((const float*)src + i);
            float4 a = s[0], b = s[1];
            __half2 p0 = __floats2half2_rn(a.x, a.y);
            __half2 p1 = __floats2half2_rn(a.z, a.w);
            __half2 p2 = __floats2half2_rn(b.x, b.y);
            __half2 p3 = __floats2half2_rn(b.z, b.w);
            o = make_uint4(*(uint32_t*)&p0, *(uint32_t*)&p1, *(uint32_t*)&p2, *(uint32_t*)&p3);
        } else if (dt == 1) {
            uint4 s = *reinterpret_cast<const uint4*>((const __nv_bfloat16*)src + i);
            uint32_t ws[4] = {s.x, s.y, s.z, s.w};
            uint32_t po[4];
#pragma unroll
            for (int j = 0; j < 4; j++) {
                float f0 = __uint_as_float(ws[j] << 16);
                float f1 = __uint_as_float(ws[j] & 0xFFFF0000u);
                __half2 p = __floats2half2_rn(f0, f1);
                po[j] = *(uint32_t*)&p;
            }
            o = make_uint4(po[0], po[1], po[2], po[3]);
        } else {
            o = *reinterpret_cast<const uint4*>((const __half*)src + i);
        }
        *reinterpret_cast<uint4*>(dst + i) = o;
    }
}
__global__ void convert_to_half_k(const void* __restrict__ src, __half* __restrict__ dst,
                                  size_t n, int mode) {
    const int dt = g_dtype;
    if (mode == 2 && dt != 2) return;
    if (mode == 1 && dt == 0) return;
    const size_t stride = (size_t)gridDim.x * blockDim.x * 8;
    conv_range(src, dst, n, dt, ((size_t)blockIdx.x * blockDim.x + threadIdx.x) * 8, stride);
}
// x + wg + wu in one launch (all gated by mode semantics of 'mode')
__global__ void convert3_to_half_k(const void* __restrict__ s0, __half* __restrict__ d0, size_t n0,
                                   const void* __restrict__ s1, __half* __restrict__ d1,
                                   const void* __restrict__ s2, __half* __restrict__ d2, size_t n12,
                                   int mode) {
    const int dt = g_dtype;
    if (mode == 2 && dt != 2) return;
    if (mode == 1 && dt == 0) return;
    const size_t stride = (size_t)gridDim.x * blockDim.x * 8;
    const size_t start = ((size_t)blockIdx.x * blockDim.x + threadIdx.x) * 8;
    conv_range(s0, d0, n0,  dt, start, stride);
    conv_range(s1, d1, n12, dt, start, stride);
    conv_range(s2, d2, n12, dt, start, stride);
}

// ---------------- asm helpers ----------------
__device__ __forceinline__ uint32_t smem_u32(const void* p) {
    uint32_t a;
    asm("{ .reg .u64 t; cvta.to.shared.u64 t, %1; cvt.u32.u64 %0, t; }" : "=r"(a) : "l"(p));
    return a;
}

#define CP_ASYNC16(smem_addr, gptr) \
    asm volatile("cp.async.cg.shared.global [%0], [%1], 16;" \
                 :: "r"(smem_addr), "l"(gptr) : "memory")
#define CP_COMMIT() asm volatile("cp.async.commit_group;" ::: "memory")
#define CP_WAIT(n)  asm volatile("cp.async.wait_group %0;" :: "n"(n) : "memory")
#define CP_WAIT_ALL() asm volatile("cp.async.wait_all;" ::: "memory")

#define MBARRIER_INIT(addr, cnt) \
    asm volatile("mbarrier.init.shared.b64 [%0], %1;" :: "r"((uint32_t)(addr)), "r"((uint32_t)(cnt)) : "memory")
#define MBARRIER_ARRIVE(addr) \
    asm volatile("mbarrier.arrive.shared.b64 _, [%0];" :: "r"((uint32_t)(addr)) : "memory")
#define MBARRIER_EXPECT_TX(addr, bytes) \
    asm volatile("mbarrier.arrive.expect_tx.shared.b64 _, [%0], %1;" :: "r"((uint32_t)(addr)), "r"((uint32_t)(bytes)) : "memory")

#define MBARRIER_WAIT_PARITY(mbar_smem_addr, phase_parity) do { \
    uint32_t _mbar = (uint32_t)(mbar_smem_addr); \
    uint32_t _parity = (uint32_t)(phase_parity); \
    uint32_t _done; \
    asm volatile( \
        "{\n\t.reg .pred p;\n\t" \
        "mbarrier.try_wait.parity.shared.b64 p, [%1], %2;\n\t" \
        "selp.b32 %0, 1, 0, p;\n\t}" \
        : "=r"(_done) : "r"(_mbar), "r"(_parity) : "memory"); \
    if (!_done) { \
        asm volatile( \
            "{\n\t.reg .pred P1;\n\t" \
            "WAIT_LOOP_%=:\n\t" \
            "mbarrier.try_wait.parity.shared.b64 P1, [%0], %1, 0x989680;\n\t" \
            "@P1 bra.uni WAIT_DONE_%=;\n\t" \
            "bra.uni WAIT_LOOP_%=;\n\t" \
            "WAIT_DONE_%=:\n\t}" \
            :: "r"(_mbar), "r"(_parity) : "memory"); \
    } \
} while(0)

#define FENCE_PROXY_ASYNC() \
    asm volatile("fence.proxy.async.shared::cta;" ::: "memory")

__device__ __forceinline__ void tma_load_2d(uint32_t smem_addr, const void* tmap,
                                            int32_t cx, int32_t cy, uint32_t mbar) {
    asm volatile(
        "cp.async.bulk.tensor.2d.shared::cta.global.tile.mbarrier::complete_tx::bytes "
        "[%0], [%1, {%2, %3}], [%4];"
        :: "r"(smem_addr), "l"(tmap), "r"(cx), "r"(cy), "r"(mbar) : "memory");
}

__device__ __forceinline__ void ldsm_x4(uint32_t& r0, uint32_t& r1, uint32_t& r2, uint32_t& r3,
                                        uint32_t addr) {
    asm volatile("ldmatrix.sync.aligned.m8n8.x4.shared.b16 {%0,%1,%2,%3}, [%4];"
                 : "=r"(r0), "=r"(r1), "=r"(r2), "=r"(r3) : "r"(addr));
}

template<bool BF16>
__device__ __forceinline__ void mma_any(float* c, const uint32_t* a, const uint32_t* b) {
    if (BF16)
        asm volatile(
            "mma.sync.aligned.m16n8k16.row.col.f32.bf16.bf16.f32 "
            "{%0,%1,%2,%3}, {%4,%5,%6,%7}, {%8,%9}, {%0,%1,%2,%3};"
            : "+f"(c[0]), "+f"(c[1]), "+f"(c[2]), "+f"(c[3])
            : "r"(a[0]), "r"(a[1]), "r"(a[2]), "r"(a[3]), "r"(b[0]), "r"(b[1]));
    else
        asm volatile(
            "mma.sync.aligned.m16n8k16.row.col.f32.f16.f16.f32 "
            "{%0,%1,%2,%3}, {%4,%5,%6,%7}, {%8,%9}, {%0,%1,%2,%3};"
            : "+f"(c[0]), "+f"(c[1]), "+f"(c[2]), "+f"(c[3])
            : "r"(a[0]), "r"(a[1]), "r"(a[2]), "r"(a[3]), "r"(b[0]), "r"(b[1]));
}

__device__ __forceinline__ void store_out_dtype(void* outv, size_t i0, size_t i1,
                                                const float* a4, int dt) {
    if (dt == 2) {
        *reinterpret_cast<float2*>((float*)outv + i0) = make_float2(a4[0], a4[1]);
        *reinterpret_cast<float2*>((float*)outv + i1) = make_float2(a4[2], a4[3]);
    } else if (dt == 1) {
        __nv_bfloat162 b0 = __floats2bfloat162_rn(a4[0], a4[1]);
        __nv_bfloat162 b1 = __floats2bfloat162_rn(a4[2], a4[3]);
        *reinterpret_cast<__nv_bfloat162*>((__nv_bfloat16*)outv + i0) = b0;
        *reinterpret_cast<__nv_bfloat162*>((__nv_bfloat16*)outv + i1) = b1;
    } else {
        *reinterpret_cast<__half2*>((__half*)outv + i0) = __floats2half2_rn(a4[0], a4[1]);
        *reinterpret_cast<__half2*>((__half*)outv + i1) = __floats2half2_rn(a4[2], a4[3]);
    }
}

// consumer mainloop (proven structure, f32-accum), templated on element type
template<bool BF16, int KITERS, int NSTAGES>
__device__ __forceinline__ void consumer_loop(
    uint32_t sb, uint32_t off_full, uint32_t off_empty, uint32_t off_tile,
    uint32_t stage_bytes, uint32_t boff,
    uint32_t a_row, uint32_t a_koff, uint32_t b_row, uint32_t b_koff, uint32_t xor7,
    int lane, float (&acc)[4][4][4])
{
    int s = 0, ph = 0;
    for (int k = 0; k < KITERS; k++) {
        MBARRIER_WAIT_PARITY(sb + off_full + s * 8, ph);
        const uint32_t stA = sb + off_tile + (uint32_t)s * stage_bytes;
        const uint32_t stB = stA + boff;
#pragma unroll
        for (int ks = 0; ks < 4; ks++) {
            const uint32_t kbA = ((uint32_t)(ks * 32) + a_koff) ^ xor7;
            const uint32_t kbB = ((uint32_t)(ks * 32) + b_koff) ^ xor7;
            uint32_t aF[4][4];
#pragma unroll
            for (int mb = 0; mb < 4; mb++)
                ldsm_x4(aF[mb][0], aF[mb][1], aF[mb][2], aF[mb][3],
                        stA + (a_row + mb * 16) * 128 + kbA);
            uint32_t bF[2][4];
#pragma unroll
            for (int nb = 0; nb < 2; nb++)
                ldsm_x4(bF[nb][0], bF[nb][1], bF[nb][2], bF[nb][3],
                        stB + (b_row + nb * 16) * 128 + kbB);
#pragma unroll
            for (int mb = 0; mb < 4; mb++)
#pragma unroll
                for (int ns = 0; ns < 4; ns++)
                    mma_any<BF16>(acc[mb][ns], aF[mb], &bF[ns >> 1][(ns & 1) * 2]);
        }
        if (lane == 0) MBARRIER_ARRIVE(sb + off_empty + s * 8);
        if (++s == NSTAGES) { s = 0; ph ^= 1; }
    }
}

// =======================================================================
// TMA GEMM (proven config: 16 compute warps 64x32 + producer = 544 thr).
// FUSED  (MTILE=128): warps 0-7 gate, 8-15 up, shared A; silu-combine -> fp16 h.
//        Epilogue 'up' exchange packed as half2 (32 KB).
// !FUSED (MTILE=256): 4x4 warp grid; store in detected dtype.
// =======================================================================
template<int MTILE, int NSTAGES, bool FUSED, int NTM, int GRP>
__global__ void __launch_bounds__(544, 1)
mlp_gemm_tma(const __grid_constant__ CUtensorMap mapAo,
             const __grid_constant__ CUtensorMap mapAc,
             const __grid_constant__ CUtensorMap mapB0o,
             const __grid_constant__ CUtensorMap mapB0c,
             const __grid_constant__ CUtensorMap mapB1o,
             const __grid_constant__ CUtensorMap mapB1c,
             void* __restrict__ outv)
{
    constexpr int KDIM       = FUSED ? HD : MDIM;
    constexpr int KITERS     = KDIM / 64;
    constexpr int OUT_STRIDE = FUSED ? MDIM : HD;
    constexpr uint32_t ATILE = (uint32_t)MTILE * 128;
    constexpr uint32_t BTILE = 128 * 128;
    constexpr uint32_t STAGE = ATILE + (FUSED ? 2 : 1) * BTILE;

    extern __shared__ char smem_raw[];
    const uint32_t raw = smem_u32(smem_raw);
    const uint32_t sb  = (raw + 1023u) & ~1023u;

    const int tid  = threadIdx.x;
    const int wid  = tid >> 5;
    const int lane = tid & 31;
    const int dt   = g_dtype;

    const uint32_t OFF_FULL  = 0;
    const uint32_t OFF_EMPTY = 256;
    const uint32_t OFF_TILE  = 1024;

    if (tid == 0) {
        for (int s = 0; s < NSTAGES; s++) {
            MBARRIER_INIT(sb + OFF_FULL  + s * 8, 1);
            MBARRIER_INIT(sb + OFF_EMPTY + s * 8, 16);
        }
        FENCE_PROXY_ASYNC();
    }
    __syncthreads();

    // swizzled rasterization: groups of GRP N-tiles x all NTM M-tiles
    const int id = blockIdx.y * gridDim.x + blockIdx.x;
    const int gper = NTM * GRP;
    const int grp = id / gper;
    const int rem = id % gper;
    const int m0 = (rem % NTM) * MTILE;
    const int n0 = (grp * GRP + rem / NTM) * 128;

    // map selection (uniform): A conv only for fp32; B conv for fp32 (FUSED) or dt!=0 (!FUSED)
    const void* pA  = (FUSED && dt == 2) ? (const void*)&mapAc  : (const void*)&mapAo;
    const bool bconv = FUSED ? (dt == 2) : (dt != 0);
    const void* pB0 = bconv ? (const void*)&mapB0c : (const void*)&mapB0o;
    const void* pB1 = bconv ? (const void*)&mapB1c : (const void*)&mapB1o;

    if (wid == 16) {
        // ---------------- TMA producer ----------------
        if (lane == 0) {
            int s = 0, ph = 1;
            for (int k = 0; k < KITERS; k++) {
                MBARRIER_WAIT_PARITY(sb + OFF_EMPTY + s * 8, ph);
                MBARRIER_EXPECT_TX(sb + OFF_FULL + s * 8, STAGE);
                const uint32_t st = sb + OFF_TILE + (uint32_t)s * STAGE;
                tma_load_2d(st,         pA,  k * 64, m0, sb + OFF_FULL + s * 8);
                tma_load_2d(st + ATILE, pB0, k * 64, n0, sb + OFF_FULL + s * 8);
                if (FUSED)
                    tma_load_2d(st + ATILE + BTILE, pB1, k * 64, n0, sb + OFF_FULL + s * 8);
                if (++s == NSTAGES) { s = 0; ph ^= 1; }
            }
        }
    } else {
        // ---------------- compute warps (64x32 tiles, proven layout) ----------------
        const int  cq    = FUSED ? (wid & 7) : wid;
        const bool is_up = FUSED && (wid >= 8);
        const int  wm0   = FUSED ? (cq & 1) * 64 : (cq & 3) * 64;
        const int  wn0   = FUSED ? (cq >> 1) * 32 : (cq >> 2) * 32;

        const uint32_t xor7   = (uint32_t)(lane & 7) << 4;
        const uint32_t a_row  = (uint32_t)(wm0 + (lane & 15));
        const uint32_t a_koff = (uint32_t)(lane & 16);
        const uint32_t b_row  = (uint32_t)(wn0 + (lane & 7) + ((lane & 16) >> 1));
        const uint32_t b_koff = (uint32_t)((lane & 8) << 1);
        const uint32_t boff   = ATILE + (is_up ? BTILE : 0);

        float acc[4][4][4];
#pragma unroll
        for (int i = 0; i < 4; i++)
#pragma unroll
            for (int j = 0; j < 4; j++)
#pragma unroll
                for (int v = 0; v < 4; v++) acc[i][j][v] = 0.0f;

        if (FUSED && dt == 1)
            consumer_loop<true,  KITERS, NSTAGES>(sb, OFF_FULL, OFF_EMPTY, OFF_TILE, STAGE,
                                                  boff, a_row, a_koff, b_row, b_koff, xor7,
                                                  lane, acc);
        else
            consumer_loop<false, KITERS, NSTAGES>(sb, OFF_FULL, OFF_EMPTY, OFF_TILE, STAGE,
                                                  boff, a_row, a_koff, b_row, b_koff, xor7,
                                                  lane, acc);

        const int g = lane >> 2, c2 = (lane & 3) * 2;

        if (!FUSED) {
#pragma unroll
            for (int mb = 0; mb < 4; mb++)
#pragma unroll
                for (int ns = 0; ns < 4; ns++) {
                    const int mrow = m0 + wm0 + mb * 16 + g;
                    const int ncol = n0 + wn0 + ns * 8 + c2;
                    store_out_dtype(outv, (size_t)mrow * OUT_STRIDE + ncol,
                                    (size_t)(mrow + 8) * OUT_STRIDE + ncol,
                                    acc[mb][ns], dt);
                }
            return;
        }

        // fused epilogue: exchange 'up' via SMEM as packed half2, silu-combine
        __syncthreads();   // (1)
        uint32_t* exch = reinterpret_cast<uint32_t*>(smem_raw + (sb - raw) + OFF_TILE);
        __half* out = reinterpret_cast<__half*>(outv);
        if (is_up) {
            const int t = (wid - 8) * 32 + lane;   // 0..255
#pragma unroll
            for (int mb = 0; mb < 4; mb++)
#pragma unroll
                for (int ns = 0; ns < 4; ns++) {
                    __half2 p0 = __floats2half2_rn(acc[mb][ns][0], acc[mb][ns][1]);
                    __half2 p1 = __floats2half2_rn(acc[mb][ns][2], acc[mb][ns][3]);
                    exch[((mb * 4 + ns) * 2 + 0) * 256 + t] = *reinterpret_cast<uint32_t*>(&p0);
                    exch[((mb * 4 + ns) * 2 + 1) * 256 + t] = *reinterpret_cast<uint32_t*>(&p1);
                }
        }
        __syncthreads();   // (2)
        if (!is_up) {
            const int t = wid * 32 + lane;
#pragma unroll
            for (int mb = 0; mb < 4; mb++)
#pragma unroll
                for (int ns = 0; ns < 4; ns++) {
                    uint32_t u0 = exch[((mb * 4 + ns) * 2 + 0) * 256 + t];
                    uint32_t u1 = exch[((mb * 4 + ns) * 2 + 1) * 256 + t];
                    const float2 up01 = __half22float2(*reinterpret_cast<__half2*>(&u0));
                    const float2 up23 = __half22float2(*reinterpret_cast<__half2*>(&u1));
                    const float upv[4] = {up01.x, up01.y, up23.x, up23.y};
                    float r[4];
#pragma unroll
                    for (int v = 0; v < 4; v++) {
                        const float gt = acc[mb][ns][v];
                        r[v] = upv[v] * (gt / (1.0f + __expf(-gt)));
                    }
                    const int mrow = m0 + wm0 + mb * 16 + g;
                    const int ncol = n0 + wn0 + ns * 8 + c2;
                    *reinterpret_cast<__half2*>(out + (size_t)mrow * OUT_STRIDE + ncol) =
                        __floats2half2_rn(r[0], r[1]);
                    *reinterpret_cast<__half2*>(out + (size_t)(mrow + 8) * OUT_STRIDE + ncol) =
                        __floats2half2_rn(r[2], r[3]);
                }
        }
        return;
    }

    if (FUSED) { __syncthreads(); __syncthreads(); }
}

// =======================================================================
// Fallback: cp.async GEMM (proven R4) — only if tensormap creation fails
// =======================================================================
template<int NTHREADS>
__device__ __forceinline__ void load_tile(uint32_t smem_tile, const __half* g,
                                          int row0, int kbyte, int ld_elems, int tid) {
    const char* gbase = reinterpret_cast<const char*>(g) + (size_t)row0 * (ld_elems * 2) + kbyte;
#pragma unroll
    for (int c = tid; c < 1024; c += NTHREADS) {
        const int row = c >> 3;
        const int col = (c & 7) << 4;
        const char* src = gbase + (size_t)row * (ld_elems * 2) + col;
        const uint32_t dst = smem_tile + row * 128 + (col ^ ((row & 7) << 4));
        CP_ASYNC16(dst, src);
    }
}

template<int NW, int NSTAGES, bool FUSED>
__global__ void __launch_bounds__(NW * 32, 1)
mlp_gemm_cp(const __half* __restrict__ A, const __half* __restrict__ B0,
            const __half* __restrict__ B1, void* __restrict__ outv)
{
    constexpr int NTH        = NW * 32;
    constexpr int KDIM       = FUSED ? HD : MDIM;
    constexpr int KITERS     = KDIM / 64;
    constexpr int OUT_STRIDE = FUSED ? MDIM : HD;
    constexpr uint32_t ATILE = 128 * 128;
    constexpr uint32_t STAGE = FUSED ? 3 * ATILE : 2 * ATILE;

    extern __shared__ char smem_raw[];
    const uint32_t raw = smem_u32(smem_raw);
    const uint32_t sb  = (raw + 127u) & ~127u;

    const int tid  = threadIdx.x;
    const int wid  = tid >> 5;
    const int lane = tid & 31;

    const int m0 = blockIdx.x * 128;
    const int n0 = blockIdx.y * 128;

    const int  cq    = FUSED ? (wid & 7) : wid;
    const bool is_up = FUSED && (wid >= 8);
    const int  wm0   = (cq & 1) * 64;
    const int  wn0   = (cq >> 1) * 32;

    const uint32_t xor7   = (uint32_t)(lane & 7) << 4;
    const uint32_t a_row  = (uint32_t)(wm0 + (lane & 15));
    const uint32_t a_koff = (uint32_t)(lane & 16);
    const uint32_t b_row  = (uint32_t)(wn0 + (lane & 7) + ((lane & 16) >> 1));
    const uint32_t b_koff = (uint32_t)((lane & 8) << 1);
    const uint32_t boff   = is_up ? 2 * ATILE : ATILE;

    float acc[4][4][4];
#pragma unroll
    for (int i = 0; i < 4; i++)
#pragma unroll
        for (int j = 0; j < 4; j++)
#pragma unroll
            for (int v = 0; v < 4; v++) acc[i][j][v] = 0.0f;

    auto load_stage = [&](int s, int k) {
        const uint32_t st = sb + (uint32_t)s * STAGE;
        const int kb = k * 128;
        load_tile<NTH>(st,         A,  m0, kb, KDIM, tid);
        load_tile<NTH>(st + ATILE, B0, n0, kb, KDIM, tid);
        if (FUSED)
            load_tile<NTH>(st + 2 * ATILE, B1, n0, kb, KDIM, tid);
    };

#pragma unroll
    for (int s = 0; s < NSTAGES - 1; s++) { load_stage(s, s); CP_COMMIT(); }

    int sc = 0;
    for (int k = 0; k < KITERS; k++) {
        CP_WAIT(NSTAGES - 2);
        __syncthreads();
        const uint32_t stA = sb + (uint32_t)sc * STAGE;
        const uint32_t stB = stA + boff;
#pragma unroll
        for (int ks = 0; ks < 4; ks++) {
            const uint32_t kbA = ((uint32_t)(ks * 32) + a_koff) ^ xor7;
            const uint32_t kbB = ((uint32_t)(ks * 32) + b_koff) ^ xor7;
            uint32_t aF[4][4];
#pragma unroll
            for (int mb = 0; mb < 4; mb++)
                ldsm_x4(aF[mb][0], aF[mb][1], aF[mb][2], aF[mb][3],
                        stA + (a_row + mb * 16) * 128 + kbA);
            uint32_t bF[2][4];
#pragma unroll
            for (int nb = 0; nb < 2; nb++)
                ldsm_x4(bF[nb][0], bF[nb][1], bF[nb][2], bF[nb][3],
                        stB + (b_row + nb * 16) * 128 + kbB);
#pragma unroll
            for (int mb = 0; mb < 4; mb++)
#pragma unroll
                for (int ns = 0; ns < 4; ns++)
                    mma_any<false>(acc[mb][ns], aF[mb], &bF[ns >> 1][(ns & 1) * 2]);
        }
        __syncthreads();
        const int kn = k + NSTAGES - 1;
        if (kn < KITERS) load_stage((sc + NSTAGES - 1) % NSTAGES, kn);
        CP_COMMIT();
        sc = (sc + 1 == NSTAGES) ? 0 : sc + 1;
    }

    const int g = lane >> 2, c2 = (lane & 3) * 2;

    if (!FUSED) {
        const int dt = g_dtype;
#pragma unroll
        for (int mb = 0; mb < 4; mb++)
#pragma unroll
            for (int ns = 0; ns < 4; ns++) {
                const int mrow = m0 + wm0 + mb * 16 + g;
                const int ncol = n0 + wn0 + ns * 8 + c2;
                store_out_dtype(outv, (size_t)mrow * OUT_STRIDE + ncol,
                                (size_t)(mrow + 8) * OUT_STRIDE + ncol, acc[mb][ns], dt);
            }
        return;
    }

    CP_WAIT_ALL();
    __syncthreads();
    float* exch = reinterpret_cast<float*>(smem_raw + (sb - raw));
    __half* out = reinterpret_cast<__half*>(outv);
    if (is_up) {
        const int t = (wid - 8) * 32 + lane;
#pragma unroll
        for (int mb = 0; mb < 4; mb++)
#pragma unroll
            for (int ns = 0; ns < 4; ns++)
#pragma unroll
                for (int v = 0; v < 4; v++)
                    exch[((mb * 4 + ns) * 4 + v) * 256 + t] = acc[mb][ns][v];
    }
    __syncthreads();
    if (!is_up) {
        const int t = wid * 32 + lane;
#pragma unroll
        for (int mb = 0; mb < 4; mb++)
#pragma unroll
            for (int ns = 0; ns < 4; ns++) {
                float r[4];
#pragma unroll
                for (int v = 0; v < 4; v++) {
                    const float gt = acc[mb][ns][v];
                    const float up = exch[((mb * 4 + ns) * 4 + v) * 256 + t];
                    r[v] = up * (gt / (1.0f + __expf(-gt)));
                }
                const int mrow = m0 + wm0 + mb * 16 + g;
                const int ncol = n0 + wn0 + ns * 8 + c2;
                *reinterpret_cast<__half2*>(out + (size_t)mrow * OUT_STRIDE + ncol) =
                    __floats2half2_rn(r[0], r[1]);
                *reinterpret_cast<__half2*>(out + (size_t)(mrow + 8) * OUT_STRIDE + ncol) =
                    __floats2half2_rn(r[2], r[3]);
            }
    }
}

// ---------------- host side ----------------
typedef CUresult (*tmap_encode_fn)(
    CUtensorMap*, CUtensorMapDataType, cuuint32_t, void*,
    const cuuint64_t*, const cuuint64_t*, const cuuint32_t*, const cuuint32_t*,
    CUtensorMapInterleave, CUtensorMapSwizzle, CUtensorMapL2promotion, CUtensorMapFloatOOBfill);

static tmap_encode_fn get_encode_fn() {
    void* fn = nullptr;
    cudaDriverEntryPointQueryResult st;
    if (cudaGetDriverEntryPointByVersion("cuTensorMapEncodeTiled", &fn, 12000,
                                         cudaEnableDefault, &st) == cudaSuccess && fn)
        return (tmap_encode_fn)fn;
    fn = nullptr;
    if (cudaGetDriverEntryPointByVersion("cuTensorMapEncodeTiled", &fn, 13000,
                                         cudaEnableDefault, &st) == cudaSuccess && fn)
        return (tmap_encode_fn)fn;
    return nullptr;
}

static CUresult build_map(tmap_encode_fn enc, CUtensorMap* m, const void* base,
                          uint64_t inner, uint64_t outer, uint32_t box_rows) {
    cuuint64_t dims[2]    = {inner, outer};
    cuuint64_t strides[1] = {inner * 2};
    cuuint32_t box[2]     = {64u, box_rows};
    cuuint32_t es[2]      = {1u, 1u};
    return enc(m, CU_TENSOR_MAP_DATA_TYPE_FLOAT16, 2, const_cast<void*>(base),
               dims, strides, box, es,
               CU_TENSOR_MAP_INTERLEAVE_NONE, CU_TENSOR_MAP_SWIZZLE_128B,
               CU_TENSOR_MAP_L2_PROMOTION_L2_128B, CU_TENSOR_MAP_FLOAT_OOB_FILL_NONE);
}

extern "C" void kernel_launch(void* const* d_in, const int* in_sizes, int n_in,
                              void* d_out, int out_size) {
    (void)in_sizes; (void)n_in; (void)out_size;

    const void* x  = d_in[0];
    const void* wg = d_in[1];
    const void* wu = d_in[2];
    const void* wd = d_in[3];

    void *px, *pwg, *pwu, *pwd, *ph;
    cudaGetSymbolAddress(&px,  g_x16);
    cudaGetSymbolAddress(&pwg, g_wg16);
    cudaGetSymbolAddress(&pwu, g_wu16);
    cudaGetSymbolAddress(&pwd, g_wd16);
    cudaGetSymbolAddress(&ph,  g_hbuf);

    detect_dtype_k<<<1, 256>>>((const uint32_t*)x);
    const size_t nx = (size_t)NTOK * HD, nw = (size_t)MDIM * HD;

    // try TMA path
    bool tma_ok = false;
    CUtensorMap mXo, mXc, mWgo, mWgc, mWuo, mWuc, mWdo, mWdc, mH;
    tmap_encode_fn enc = get_encode_fn();
    if (enc) {
        CUresult r;
        tma_ok = true;
        r = build_map(enc, &mXo,  x,   HD,   NTOK, 128); tma_ok &= (r == CUDA_SUCCESS);
        r = build_map(enc, &mXc,  px,  HD,   NTOK, 128); tma_ok &= (r == CUDA_SUCCESS);
        r = build_map(enc, &mWgo, wg,  HD,   MDIM, 128); tma_ok &= (r == CUDA_SUCCESS);
        r = build_map(enc, &mWgc, pwg, HD,   MDIM, 128); tma_ok &= (r == CUDA_SUCCESS);
        r = build_map(enc, &mWuo, wu,  HD,   MDIM, 128); tma_ok &= (r == CUDA_SUCCESS);
        r = build_map(enc, &mWuc, pwu, HD,   MDIM, 128); tma_ok &= (r == CUDA_SUCCESS);
        r = build_map(enc, &mWdo, wd,  MDIM, HD,   128); tma_ok &= (r == CUDA_SUCCESS);
        r = build_map(enc, &mWdc, pwd, MDIM, HD,   128); tma_ok &= (r == CUDA_SUCCESS);
        r = build_map(enc, &mH,   ph,  MDIM, NTOK, 256); tma_ok &= (r == CUDA_SUCCESS);
    }

    if (tma_ok) {
        // conditional conversions: x/wg/wu only if fp32 (1 launch); wd if not fp16
        convert3_to_half_k<<<(int)(nw / 2048), 256>>>(x, (__half*)px, nx,
                                                      wg, (__half*)pwg,
                                                      wu, (__half*)pwu, nw, 2);
        convert_to_half_k<<<(int)(nw / 2048), 256>>>(wd, (__half*)pwd, nw, 1);

        constexpr int SMEM1 = 2048 + 4 * 48 * 1024;
        constexpr int SMEM2 = 2048 + 4 * 48 * 1024;
        cudaFuncSetAttribute((const void*)mlp_gemm_tma<128, 4, true, 64, 4>,
                             cudaFuncAttributeMaxDynamicSharedMemorySize, SMEM1);
        cudaFuncSetAttribute((const void*)mlp_gemm_tma<256, 4, false, 32, 4>,
                             cudaFuncAttributeMaxDynamicSharedMemorySize, SMEM2);

        mlp_gemm_tma<128, 4, true, 64, 4><<<dim3(NTOK / 128, MDIM / 128), 544, SMEM1>>>(
            mXo, mXc, mWgo, mWgc, mWuo, mWuc, ph);
        mlp_gemm_tma<256, 4, false, 32, 4><<<dim3(NTOK / 256, HD / 128), 544, SMEM2>>>(
            mH, mH, mWdo, mWdc, mWdo, mWdc, d_out);
    } else {
        // fallback: full conversion + proven cp.async kernels
        convert3_to_half_k<<<(int)(nw / 2048), 256>>>(x, (__half*)px, nx,
                                                      wg, (__half*)pwg,
                                                      wu, (__half*)pwu, nw, 0);
        convert_to_half_k<<<(int)(nw / 2048), 256>>>(wd, (__half*)pwd, nw, 0);

        constexpr int SMEM1 = 4 * (3 * 128 * 128) + 256;
        constexpr int SMEM2 = 5 * (2 * 128 * 128) + 256;
        cudaFuncSetAttribute((const void*)mlp_gemm_cp<16, 4, true>,
                             cudaFuncAttributeMaxDynamicSharedMemorySize, SMEM1);
        cudaFuncSetAttribute((const void*)mlp_gemm_cp<8, 5, false>,
                             cudaFuncAttributeMaxDynamicSharedMemorySize, SMEM2);

        mlp_gemm_cp<16, 4, true><<<dim3(NTOK / 128, MDIM / 128), 512, SMEM1>>>(
            (__half*)px, (__half*)pwg, (__half*)pwu, ph);
        mlp_gemm_cp<8, 5, false><<<dim3(NTOK / 128, HD / 128), 256, SMEM2>>>(
            (__half*)ph, (__half*)pwd, (__half*)pwd, d_out);
    }
}

// round 15
// speedup vs baseline: 1.0028x; 1.0014x over previous
#include <cuda_runtime.h>
#include <cuda_fp16.h>
#include <cuda_bf16.h>
#include <cuda.h>
#include <cstdint>

// ---------------- problem dims ----------------
static constexpr int HD   = 4096;
static constexpr int MDIM = 14336;
static constexpr int NTOK = 8192;   // 4 * 2048 tokens

// fp16 scratch (used only when needed) + intermediate h (always fp16)
__device__ __align__(1024) __half g_x16[(size_t)NTOK * HD];
__device__ __align__(1024) __half g_wg16[(size_t)MDIM * HD];
__device__ __align__(1024) __half g_wu16[(size_t)MDIM * HD];
__device__ __align__(1024) __half g_wd16[(size_t)HD * MDIM];
__device__ __align__(1024) __half g_hbuf[(size_t)NTOK * MDIM];
__device__ int g_dtype;   // 0 = fp16, 1 = bf16, 2 = fp32

// ---------------- dtype detector ----------------
__device__ __forceinline__ bool plaus_f(float v) {
    return isfinite(v) && fabsf(v) > 1e-4f && fabsf(v) < 100.0f;
}
__device__ __forceinline__ float h_bits(uint32_t b) {
    __half_raw r; r.x = (unsigned short)b;
    return __half2float(*reinterpret_cast<__half*>(&r));
}
__global__ void detect_dtype_k(const uint32_t* __restrict__ w) {
    __shared__ int c[3];
    if (threadIdx.x < 3) c[threadIdx.x] = 0;
    __syncthreads();
    int c16 = 0, cb = 0, c32 = 0;
    for (int i = threadIdx.x; i < 8192; i += 256) {
        uint32_t v = w[i];
        if (plaus_f(__uint_as_float(v))) c32++;
        uint32_t lo = v & 0xFFFFu, hi = v >> 16;
        if (plaus_f(h_bits(lo)) && plaus_f(h_bits(hi))) c16++;
        if (plaus_f(__uint_as_float(lo << 16)) && plaus_f(__uint_as_float(v & 0xFFFF0000u))) cb++;
    }
    atomicAdd(&c[0], c16); atomicAdd(&c[1], cb); atomicAdd(&c[2], c32);
    __syncthreads();
    if (threadIdx.x == 0) {
        const int thresh = (8192 * 9) / 10;
        int dt;
        if (c[1] > thresh)      dt = 1;
        else if (c[0] > thresh) dt = 0;
        else                    dt = 2;
        g_dtype = dt;
    }
}

// ---------------- conditional conversion -> fp16 ----------------
// mode 0: always convert; mode 2: only if dt==2 (fp32); mode 1: if dt != 0
__device__ __forceinline__ void conv_range(const void* src, __half* dst, size_t n,
                                           int dt, size_t start, size_t stride) {
    for (size_t i = start; i < n; i += stride) {
        uint4 o;
        if (dt == 2) {
            const float4* s = reinterpret_cast<const float4*>((const float*)src + i);
            float4 a = s[0], b = s[1];
            __half2 p0 = __floats2half2_rn(a.x, a.y);
            __half2 p1 = __floats2half2_rn(a.z, a.w);
            __half2 p2 = __floats2half2_rn(b.x, b.y);
            __half2 p3 = __floats2half2_rn(b.z, b.w);
            o = make_uint4(*(uint32_t*)&p0, *(uint32_t*)&p1, *(uint32_t*)&p2, *(uint32_t*)&p3);
        } else if (dt == 1) {
            uint4 s = *reinterpret_cast<const uint4*>((const __nv_bfloat16*)src + i);
            uint32_t ws[4] = {s.x, s.y, s.z, s.w};
            uint32_t po[4];
#pragma unroll
            for (int j = 0; j < 4; j++) {
                float f0 = __uint_as_float(ws[j] << 16);
                float f1 = __uint_as_float(ws[j] & 0xFFFF0000u);
                __half2 p = __floats2half2_rn(f0, f1);
                po[j] = *(uint32_t*)&p;
            }
            o = make_uint4(po[0], po[1], po[2], po[3]);
        } else {
            o = *reinterpret_cast<const uint4*>((const __half*)src + i);
        }
        *reinterpret_cast<uint4*>(dst + i) = o;
    }
}
__global__ void convert_to_half_k(const void* __restrict__ src, __half* __restrict__ dst,
                                  size_t n, int mode) {
    const int dt = g_dtype;
    if (mode == 2 && dt != 2) return;
    if (mode == 1 && dt == 0) return;
    const size_t stride = (size_t)gridDim.x * blockDim.x * 8;
    conv_range(src, dst, n, dt, ((size_t)blockIdx.x * blockDim.x + threadIdx.x) * 8, stride);
}
// x + wg + wu in one launch (all gated by mode semantics of 'mode')
__global__ void convert3_to_half_k(const void* __restrict__ s0, __half* __restrict__ d0, size_t n0,
                                   const void* __restrict__ s1, __half* __restrict__ d1,
                                   const void* __restrict__ s2, __half* __restrict__ d2, size_t n12,
                                   int mode) {
    const int dt = g_dtype;
    if (mode == 2 && dt != 2) return;
    if (mode == 1 && dt == 0) return;
    const size_t stride = (size_t)gridDim.x * blockDim.x * 8;
    const size_t start = ((size_t)blockIdx.x * blockDim.x + threadIdx.x) * 8;
    conv_range(s0, d0, n0,  dt, start, stride);
    conv_range(s1, d1, n12, dt, start, stride);
    conv_range(s2, d2, n12, dt, start, stride);
}

// ---------------- asm helpers ----------------
__device__ __forceinline__ uint32_t smem_u32(const void* p) {
    uint32_t a;
    asm("{ .reg .u64 t; cvta.to.shared.u64 t, %1; cvt.u32.u64 %0, t; }" : "=r"(a) : "l"(p));
    return a;
}

#define CP_ASYNC16(smem_addr, gptr) \
    asm volatile("cp.async.cg.shared.global [%0], [%1], 16;" \
                 :: "r"(smem_addr), "l"(gptr) : "memory")
#define CP_COMMIT() asm volatile("cp.async.commit_group;" ::: "memory")
#define CP_WAIT(n)  asm volatile("cp.async.wait_group %0;" :: "n"(n) : "memory")
#define CP_WAIT_ALL() asm volatile("cp.async.wait_all;" ::: "memory")

#define MBARRIER_INIT(addr, cnt) \
    asm volatile("mbarrier.init.shared.b64 [%0], %1;" :: "r"((uint32_t)(addr)), "r"((uint32_t)(cnt)) : "memory")
#define MBARRIER_ARRIVE(addr) \
    asm volatile("mbarrier.arrive.shared.b64 _, [%0];" :: "r"((uint32_t)(addr)) : "memory")
#define MBARRIER_EXPECT_TX(addr, bytes) \
    asm volatile("mbarrier.arrive.expect_tx.shared.b64 _, [%0], %1;" :: "r"((uint32_t)(addr)), "r"((uint32_t)(bytes)) : "memory")

#define MBARRIER_WAIT_PARITY(mbar_smem_addr, phase_parity) do { \
    uint32_t _mbar = (uint32_t)(mbar_smem_addr); \
    uint32_t _parity = (uint32_t)(phase_parity); \
    uint32_t _done; \
    asm volatile( \
        "{\n\t.reg .pred p;\n\t" \
        "mbarrier.try_wait.parity.shared.b64 p, [%1], %2;\n\t" \
        "selp.b32 %0, 1, 0, p;\n\t}" \
        : "=r"(_done) : "r"(_mbar), "r"(_parity) : "memory"); \
    if (!_done) { \
        asm volatile( \
            "{\n\t.reg .pred P1;\n\t" \
            "WAIT_LOOP_%=:\n\t" \
            "mbarrier.try_wait.parity.shared.b64 P1, [%0], %1, 0x989680;\n\t" \
            "@P1 bra.uni WAIT_DONE_%=;\n\t" \
            "bra.uni WAIT_LOOP_%=;\n\t" \
            "WAIT_DONE_%=:\n\t}" \
            :: "r"(_mbar), "r"(_parity) : "memory"); \
    } \
} while(0)

#define FENCE_PROXY_ASYNC() \
    asm volatile("fence.proxy.async.shared::cta;" ::: "memory")

__device__ __forceinline__ void tma_load_2d(uint32_t smem_addr, const void* tmap,
                                            int32_t cx, int32_t cy, uint32_t mbar) {
    asm volatile(
        "cp.async.bulk.tensor.2d.shared::cta.global.tile.mbarrier::complete_tx::bytes "
        "[%0], [%1, {%2, %3}], [%4];"
        :: "r"(smem_addr), "l"(tmap), "r"(cx), "r"(cy), "r"(mbar) : "memory");
}

__device__ __forceinline__ void ldsm_x4(uint32_t& r0, uint32_t& r1, uint32_t& r2, uint32_t& r3,
                                        uint32_t addr) {
    asm volatile("ldmatrix.sync.aligned.m8n8.x4.shared.b16 {%0,%1,%2,%3}, [%4];"
                 : "=r"(r0), "=r"(r1), "=r"(r2), "=r"(r3) : "r"(addr));
}

template<bool BF16>
__device__ __forceinline__ void mma_any(float* c, const uint32_t* a, const uint32_t* b) {
    if (BF16)
        asm volatile(
            "mma.sync.aligned.m16n8k16.row.col.f32.bf16.bf16.f32 "
            "{%0,%1,%2,%3}, {%4,%5,%6,%7}, {%8,%9}, {%0,%1,%2,%3};"
            : "+f"(c[0]), "+f"(c[1]), "+f"(c[2]), "+f"(c[3])
            : "r"(a[0]), "r"(a[1]), "r"(a[2]), "r"(a[3]), "r"(b[0]), "r"(b[1]));
    else
        asm volatile(
            "mma.sync.aligned.m16n8k16.row.col.f32.f16.f16.f32 "
            "{%0,%1,%2,%3}, {%4,%5,%6,%7}, {%8,%9}, {%0,%1,%2,%3};"
            : "+f"(c[0]), "+f"(c[1]), "+f"(c[2]), "+f"(c[3])
            : "r"(a[0]), "r"(a[1]), "r"(a[2]), "r"(a[3]), "r"(b[0]), "r"(b[1]));
}

__device__ __forceinline__ void store_out_dtype(void* outv, size_t i0, size_t i1,
                                                const float* a4, int dt) {
    if (dt == 2) {
        *reinterpret_cast<float2*>((float*)outv + i0) = make_float2(a4[0], a4[1]);
        *reinterpret_cast<float2*>((float*)outv + i1) = make_float2(a4[2], a4[3]);
    } else if (dt == 1) {
        __nv_bfloat162 b0 = __floats2bfloat162_rn(a4[0], a4[1]);
        __nv_bfloat162 b1 = __floats2bfloat162_rn(a4[2], a4[3]);
        *reinterpret_cast<__nv_bfloat162*>((__nv_bfloat16*)outv + i0) = b0;
        *reinterpret_cast<__nv_bfloat162*>((__nv_bfloat16*)outv + i1) = b1;
    } else {
        *reinterpret_cast<__half2*>((__half*)outv + i0) = __floats2half2_rn(a4[0], a4[1]);
        *reinterpret_cast<__half2*>((__half*)outv + i1) = __floats2half2_rn(a4[2], a4[3]);
    }
}

// consumer mainloop with A-fragment double buffering: prefetch ks+1's A LDSMs
// during ks's MMAs. Math order identical to the proven loop (same MMA sequence).
// Register budget: acc 64 + aF 32 + bF 8 + addressing ~12 <= 120-reg cap @544thr.
template<bool BF16, int KITERS, int NSTAGES>
__device__ __forceinline__ void consumer_loop(
    uint32_t sb, uint32_t off_full, uint32_t off_empty, uint32_t off_tile,
    uint32_t stage_bytes, uint32_t boff,
    uint32_t a_row, uint32_t a_koff, uint32_t b_row, uint32_t b_koff, uint32_t xor7,
    int lane, float (&acc)[4][4][4])
{
    int s = 0, ph = 0;
    for (int k = 0; k < KITERS; k++) {
        MBARRIER_WAIT_PARITY(sb + off_full + s * 8, ph);
        const uint32_t stA = sb + off_tile + (uint32_t)s * stage_bytes;
        const uint32_t stB = stA + boff;

        uint32_t aF[2][4][4];
        // preload ks=0 A fragments
        {
            const uint32_t kbA0 = a_koff ^ xor7;
#pragma unroll
            for (int mb = 0; mb < 4; mb++)
                ldsm_x4(aF[0][mb][0], aF[0][mb][1], aF[0][mb][2], aF[0][mb][3],
                        stA + (a_row + mb * 16) * 128 + kbA0);
        }
#pragma unroll
        for (int ks = 0; ks < 4; ks++) {
            const int cur = ks & 1;
            const uint32_t kbB = ((uint32_t)(ks * 32) + b_koff) ^ xor7;
            uint32_t bF[2][4];
#pragma unroll
            for (int nb = 0; nb < 2; nb++)
                ldsm_x4(bF[nb][0], bF[nb][1], bF[nb][2], bF[nb][3],
                        stB + (b_row + nb * 16) * 128 + kbB);
            if (ks < 3) {
                // prefetch next ks's A fragments; overlaps with this ks's MMAs
                const uint32_t kbA = ((uint32_t)((ks + 1) * 32) + a_koff) ^ xor7;
#pragma unroll
                for (int mb = 0; mb < 4; mb++)
                    ldsm_x4(aF[cur ^ 1][mb][0], aF[cur ^ 1][mb][1],
                            aF[cur ^ 1][mb][2], aF[cur ^ 1][mb][3],
                            stA + (a_row + mb * 16) * 128 + kbA);
            }
#pragma unroll
            for (int mb = 0; mb < 4; mb++)
#pragma unroll
                for (int ns = 0; ns < 4; ns++)
                    mma_any<BF16>(acc[mb][ns], aF[cur][mb], &bF[ns >> 1][(ns & 1) * 2]);
        }
        if (lane == 0) MBARRIER_ARRIVE(sb + off_empty + s * 8);
        if (++s == NSTAGES) { s = 0; ph ^= 1; }
    }
}

// =======================================================================
// TMA GEMM (proven config: 16 compute warps 64x32 + producer = 544 thr).
// FUSED  (MTILE=128): warps 0-7 gate, 8-15 up, shared A; silu-combine -> fp16 h.
//        Epilogue 'up' exchange packed as half2 (32 KB).
// !FUSED (MTILE=256): 4x4 warp grid; store in detected dtype.
// =======================================================================
template<int MTILE, int NSTAGES, bool FUSED, int NTM, int GRP>
__global__ void __launch_bounds__(544, 1)
mlp_gemm_tma(const __grid_constant__ CUtensorMap mapAo,
             const __grid_constant__ CUtensorMap mapAc,
             const __grid_constant__ CUtensorMap mapB0o,
             const __grid_constant__ CUtensorMap mapB0c,
             const __grid_constant__ CUtensorMap mapB1o,
             const __grid_constant__ CUtensorMap mapB1c,
             void* __restrict__ outv)
{
    constexpr int KDIM       = FUSED ? HD : MDIM;
    constexpr int KITERS     = KDIM / 64;
    constexpr int OUT_STRIDE = FUSED ? MDIM : HD;
    constexpr uint32_t ATILE = (uint32_t)MTILE * 128;
    constexpr uint32_t BTILE = 128 * 128;
    constexpr uint32_t STAGE = ATILE + (FUSED ? 2 : 1) * BTILE;

    extern __shared__ char smem_raw[];
    const uint32_t raw = smem_u32(smem_raw);
    const uint32_t sb  = (raw + 1023u) & ~1023u;

    const int tid  = threadIdx.x;
    const int wid  = tid >> 5;
    const int lane = tid & 31;
    const int dt   = g_dtype;

    const uint32_t OFF_FULL  = 0;
    const uint32_t OFF_EMPTY = 256;
    const uint32_t OFF_TILE  = 1024;

    if (tid == 0) {
        for (int s = 0; s < NSTAGES; s++) {
            MBARRIER_INIT(sb + OFF_FULL  + s * 8, 1);
            MBARRIER_INIT(sb + OFF_EMPTY + s * 8, 16);
        }
        FENCE_PROXY_ASYNC();
    }
    __syncthreads();

    // swizzled rasterization: groups of GRP N-tiles x all NTM M-tiles
    const int id = blockIdx.y * gridDim.x + blockIdx.x;
    const int gper = NTM * GRP;
    const int grp = id / gper;
    const int rem = id % gper;
    const int m0 = (rem % NTM) * MTILE;
    const int n0 = (grp * GRP + rem / NTM) * 128;

    // map selection (uniform): A conv only for fp32; B conv for fp32 (FUSED) or dt!=0 (!FUSED)
    const void* pA  = (FUSED && dt == 2) ? (const void*)&mapAc  : (const void*)&mapAo;
    const bool bconv = FUSED ? (dt == 2) : (dt != 0);
    const void* pB0 = bconv ? (const void*)&mapB0c : (const void*)&mapB0o;
    const void* pB1 = bconv ? (const void*)&mapB1c : (const void*)&mapB1o;

    if (wid == 16) {
        // ---------------- TMA producer ----------------
        if (lane == 0) {
            int s = 0, ph = 1;
            for (int k = 0; k < KITERS; k++) {
                MBARRIER_WAIT_PARITY(sb + OFF_EMPTY + s * 8, ph);
                MBARRIER_EXPECT_TX(sb + OFF_FULL + s * 8, STAGE);
                const uint32_t st = sb + OFF_TILE + (uint32_t)s * STAGE;
                tma_load_2d(st,         pA,  k * 64, m0, sb + OFF_FULL + s * 8);
                tma_load_2d(st + ATILE, pB0, k * 64, n0, sb + OFF_FULL + s * 8);
                if (FUSED)
                    tma_load_2d(st + ATILE + BTILE, pB1, k * 64, n0, sb + OFF_FULL + s * 8);
                if (++s == NSTAGES) { s = 0; ph ^= 1; }
            }
        }
    } else {
        // ---------------- compute warps (64x32 tiles, proven layout) ----------------
        const int  cq    = FUSED ? (wid & 7) : wid;
        const bool is_up = FUSED && (wid >= 8);
        const int  wm0   = FUSED ? (cq & 1) * 64 : (cq & 3) * 64;
        const int  wn0   = FUSED ? (cq >> 1) * 32 : (cq >> 2) * 32;

        const uint32_t xor7   = (uint32_t)(lane & 7) << 4;
        const uint32_t a_row  = (uint32_t)(wm0 + (lane & 15));
        const uint32_t a_koff = (uint32_t)(lane & 16);
        const uint32_t b_row  = (uint32_t)(wn0 + (lane & 7) + ((lane & 16) >> 1));
        const uint32_t b_koff = (uint32_t)((lane & 8) << 1);
        const uint32_t boff   = ATILE + (is_up ? BTILE : 0);

        float acc[4][4][4];
#pragma unroll
        for (int i = 0; i < 4; i++)
#pragma unroll
            for (int j = 0; j < 4; j++)
#pragma unroll
                for (int v = 0; v < 4; v++) acc[i][j][v] = 0.0f;

        if (FUSED && dt == 1)
            consumer_loop<true,  KITERS, NSTAGES>(sb, OFF_FULL, OFF_EMPTY, OFF_TILE, STAGE,
                                                  boff, a_row, a_koff, b_row, b_koff, xor7,
                                                  lane, acc);
        else
            consumer_loop<false, KITERS, NSTAGES>(sb, OFF_FULL, OFF_EMPTY, OFF_TILE, STAGE,
                                                  boff, a_row, a_koff, b_row, b_koff, xor7,
                                                  lane, acc);

        const int g = lane >> 2, c2 = (lane & 3) * 2;

        if (!FUSED) {
#pragma unroll
            for (int mb = 0; mb < 4; mb++)
#pragma unroll
                for (int ns = 0; ns < 4; ns++) {
                    const int mrow = m0 + wm0 + mb * 16 + g;
                    const int ncol = n0 + wn0 + ns * 8 + c2;
                    store_out_dtype(outv, (size_t)mrow * OUT_STRIDE + ncol,
                                    (size_t)(mrow + 8) * OUT_STRIDE + ncol,
                                    acc[mb][ns], dt);
                }
            return;
        }

        // fused epilogue: exchange 'up' via SMEM as packed half2, silu-combine
        __syncthreads();   // (1)
        uint32_t* exch = reinterpret_cast<uint32_t*>(smem_raw + (sb - raw) + OFF_TILE);
        __half* out = reinterpret_cast<__half*>(outv);
        if (is_up) {
            const int t = (wid - 8) * 32 + lane;   // 0..255
#pragma unroll
            for (int mb = 0; mb < 4; mb++)
#pragma unroll
                for (int ns = 0; ns < 4; ns++) {
                    __half2 p0 = __floats2half2_rn(acc[mb][ns][0], acc[mb][ns][1]);
                    __half2 p1 = __floats2half2_rn(acc[mb][ns][2], acc[mb][ns][3]);
                    exch[((mb * 4 + ns) * 2 + 0) * 256 + t] = *reinterpret_cast<uint32_t*>(&p0);
                    exch[((mb * 4 + ns) * 2 + 1) * 256 + t] = *reinterpret_cast<uint32_t*>(&p1);
                }
        }
        __syncthreads();   // (2)
        if (!is_up) {
            const int t = wid * 32 + lane;
#pragma unroll
            for (int mb = 0; mb < 4; mb++)
#pragma unroll
                for (int ns = 0; ns < 4; ns++) {
                    uint32_t u0 = exch[((mb * 4 + ns) * 2 + 0) * 256 + t];
                    uint32_t u1 = exch[((mb * 4 + ns) * 2 + 1) * 256 + t];
                    const float2 up01 = __half22float2(*reinterpret_cast<__half2*>(&u0));
                    const float2 up23 = __half22float2(*reinterpret_cast<__half2*>(&u1));
                    const float upv[4] = {up01.x, up01.y, up23.x, up23.y};
                    float r[4];
#pragma unroll
                    for (int v = 0; v < 4; v++) {
                        const float gt = acc[mb][ns][v];
                        r[v] = upv[v] * (gt / (1.0f + __expf(-gt)));
                    }
                    const int mrow = m0 + wm0 + mb * 16 + g;
                    const int ncol = n0 + wn0 + ns * 8 + c2;
                    *reinterpret_cast<__half2*>(out + (size_t)mrow * OUT_STRIDE + ncol) =
                        __floats2half2_rn(r[0], r[1]);
                    *reinterpret_cast<__half2*>(out + (size_t)(mrow + 8) * OUT_STRIDE + ncol) =
                        __floats2half2_rn(r[2], r[3]);
                }
        }
        return;
    }

    if (FUSED) { __syncthreads(); __syncthreads(); }
}

// =======================================================================
// Fallback: cp.async GEMM (proven R4) — only if tensormap creation fails
// =======================================================================
template<int NTHREADS>
__device__ __forceinline__ void load_tile(uint32_t smem_tile, const __half* g,
                                          int row0, int kbyte, int ld_elems, int tid) {
    const char* gbase = reinterpret_cast<const char*>(g) + (size_t)row0 * (ld_elems * 2) + kbyte;
#pragma unroll
    for (int c = tid; c < 1024; c += NTHREADS) {
        const int row = c >> 3;
        const int col = (c & 7) << 4;
        const char* src = gbase + (size_t)row * (ld_elems * 2) + col;
        const uint32_t dst = smem_tile + row * 128 + (col ^ ((row & 7) << 4));
        CP_ASYNC16(dst, src);
    }
}

template<int NW, int NSTAGES, bool FUSED>
__global__ void __launch_bounds__(NW * 32, 1)
mlp_gemm_cp(const __half* __restrict__ A, const __half* __restrict__ B0,
            const __half* __restrict__ B1, void* __restrict__ outv)
{
    constexpr int NTH        = NW * 32;
    constexpr int KDIM       = FUSED ? HD : MDIM;
    constexpr int KITERS     = KDIM / 64;
    constexpr int OUT_STRIDE = FUSED ? MDIM : HD;
    constexpr uint32_t ATILE = 128 * 128;
    constexpr uint32_t STAGE = FUSED ? 3 * ATILE : 2 * ATILE;

    extern __shared__ char smem_raw[];
    const uint32_t raw = smem_u32(smem_raw);
    const uint32_t sb  = (raw + 127u) & ~127u;

    const int tid  = threadIdx.x;
    const int wid  = tid >> 5;
    const int lane = tid & 31;

    const int m0 = blockIdx.x * 128;
    const int n0 = blockIdx.y * 128;

    const int  cq    = FUSED ? (wid & 7) : wid;
    const bool is_up = FUSED && (wid >= 8);
    const int  wm0   = (cq & 1) * 64;
    const int  wn0   = (cq >> 1) * 32;

    const uint32_t xor7   = (uint32_t)(lane & 7) << 4;
    const uint32_t a_row  = (uint32_t)(wm0 + (lane & 15));
    const uint32_t a_koff = (uint32_t)(lane & 16);
    const uint32_t b_row  = (uint32_t)(wn0 + (lane & 7) + ((lane & 16) >> 1));
    const uint32_t b_koff = (uint32_t)((lane & 8) << 1);
    const uint32_t boff   = is_up ? 2 * ATILE : ATILE;

    float acc[4][4][4];
#pragma unroll
    for (int i = 0; i < 4; i++)
#pragma unroll
        for (int j = 0; j < 4; j++)
#pragma unroll
            for (int v = 0; v < 4; v++) acc[i][j][v] = 0.0f;

    auto load_stage = [&](int s, int k) {
        const uint32_t st = sb + (uint32_t)s * STAGE;
        const int kb = k * 128;
        load_tile<NTH>(st,         A,  m0, kb, KDIM, tid);
        load_tile<NTH>(st + ATILE, B0, n0, kb, KDIM, tid);
        if (FUSED)
            load_tile<NTH>(st + 2 * ATILE, B1, n0, kb, KDIM, tid);
    };

#pragma unroll
    for (int s = 0; s < NSTAGES - 1; s++) { load_stage(s, s); CP_COMMIT(); }

    int sc = 0;
    for (int k = 0; k < KITERS; k++) {
        CP_WAIT(NSTAGES - 2);
        __syncthreads();
        const uint32_t stA = sb + (uint32_t)sc * STAGE;
        const uint32_t stB = stA + boff;
#pragma unroll
        for (int ks = 0; ks < 4; ks++) {
            const uint32_t kbA = ((uint32_t)(ks * 32) + a_koff) ^ xor7;
            const uint32_t kbB = ((uint32_t)(ks * 32) + b_koff) ^ xor7;
            uint32_t aF[4][4];
#pragma unroll
            for (int mb = 0; mb < 4; mb++)
                ldsm_x4(aF[mb][0], aF[mb][1], aF[mb][2], aF[mb][3],
                        stA + (a_row + mb * 16) * 128 + kbA);
            uint32_t bF[2][4];
#pragma unroll
            for (int nb = 0; nb < 2; nb++)
                ldsm_x4(bF[nb][0], bF[nb][1], bF[nb][2], bF[nb][3],
                        stB + (b_row + nb * 16) * 128 + kbB);
#pragma unroll
            for (int mb = 0; mb < 4; mb++)
#pragma unroll
                for (int ns = 0; ns < 4; ns++)
                    mma_any<false>(acc[mb][ns], aF[mb], &bF[ns >> 1][(ns & 1) * 2]);
        }
        __syncthreads();
        const int kn = k + NSTAGES - 1;
        if (kn < KITERS) load_stage((sc + NSTAGES - 1) % NSTAGES, kn);
        CP_COMMIT();
        sc = (sc + 1 == NSTAGES) ? 0 : sc + 1;
    }

    const int g = lane >> 2, c2 = (lane & 3) * 2;

    if (!FUSED) {
        const int dt = g_dtype;
#pragma unroll
        for (int mb = 0; mb < 4; mb++)
#pragma unroll
            for (int ns = 0; ns < 4; ns++) {
                const int mrow = m0 + wm0 + mb * 16 + g;
                const int ncol = n0 + wn0 + ns * 8 + c2;
                store_out_dtype(outv, (size_t)mrow * OUT_STRIDE + ncol,
                                (size_t)(mrow + 8) * OUT_STRIDE + ncol, acc[mb][ns], dt);
            }
        return;
    }

    CP_WAIT_ALL();
    __syncthreads();
    float* exch = reinterpret_cast<float*>(smem_raw + (sb - raw));
    __half* out = reinterpret_cast<__half*>(outv);
    if (is_up) {
        const int t = (wid - 8) * 32 + lane;
#pragma unroll
        for (int mb = 0; mb < 4; mb++)
#pragma unroll
            for (int ns = 0; ns < 4; ns++)
#pragma unroll
                for (int v = 0; v < 4; v++)
                    exch[((mb * 4 + ns) * 4 + v) * 256 + t] = acc[mb][ns][v];
    }
    __syncthreads();
    if (!is_up) {
        const int t = wid * 32 + lane;
#pragma unroll
        for (int mb = 0; mb < 4; mb++)
#pragma unroll
            for (int ns = 0; ns < 4; ns++) {
                float r[4];
#pragma unroll
                for (int v = 0; v < 4; v++) {
                    const float gt = acc[mb][ns][v];
                    const float up = exch[((mb * 4 + ns) * 4 + v) * 256 + t];
                    r[v] = up * (gt / (1.0f + __expf(-gt)));
                }
                const int mrow = m0 + wm0 + mb * 16 + g;
                const int ncol = n0 + wn0 + ns * 8 + c2;
                *reinterpret_cast<__half2*>(out + (size_t)mrow * OUT_STRIDE + ncol) =
                    __floats2half2_rn(r[0], r[1]);
                *reinterpret_cast<__half2*>(out + (size_t)(mrow + 8) * OUT_STRIDE + ncol) =
                    __floats2half2_rn(r[2], r[3]);
            }
    }
}

// ---------------- host side ----------------
typedef CUresult (*tmap_encode_fn)(
    CUtensorMap*, CUtensorMapDataType, cuuint32_t, void*,
    const cuuint64_t*, const cuuint64_t*, const cuuint32_t*, const cuuint32_t*,
    CUtensorMapInterleave, CUtensorMapSwizzle, CUtensorMapL2promotion, CUtensorMapFloatOOBfill);

static tmap_encode_fn get_encode_fn() {
    void* fn = nullptr;
    cudaDriverEntryPointQueryResult st;
    if (cudaGetDriverEntryPointByVersion("cuTensorMapEncodeTiled", &fn, 12000,
                                         cudaEnableDefault, &st) == cudaSuccess && fn)
        return (tmap_encode_fn)fn;
    fn = nullptr;
    if (cudaGetDriverEntryPointByVersion("cuTensorMapEncodeTiled", &fn, 13000,
                                         cudaEnableDefault, &st) == cudaSuccess && fn)
        return (tmap_encode_fn)fn;
    return nullptr;
}

static CUresult build_map(tmap_encode_fn enc, CUtensorMap* m, const void* base,
                          uint64_t inner, uint64_t outer, uint32_t box_rows) {
    cuuint64_t dims[2]    = {inner, outer};
    cuuint64_t strides[1] = {inner * 2};
    cuuint32_t box[2]     = {64u, box_rows};
    cuuint32_t es[2]      = {1u, 1u};
    return enc(m, CU_TENSOR_MAP_DATA_TYPE_FLOAT16, 2, const_cast<void*>(base),
               dims, strides, box, es,
               CU_TENSOR_MAP_INTERLEAVE_NONE, CU_TENSOR_MAP_SWIZZLE_128B,
               CU_TENSOR_MAP_L2_PROMOTION_L2_128B, CU_TENSOR_MAP_FLOAT_OOB_FILL_NONE);
}

extern "C" void kernel_launch(void* const* d_in, const int* in_sizes, int n_in,
                              void* d_out, int out_size) {
    (void)in_sizes; (void)n_in; (void)out_size;

    const void* x  = d_in[0];
    const void* wg = d_in[1];
    const void* wu = d_in[2];
    const void* wd = d_in[3];

    void *px, *pwg, *pwu, *pwd, *ph;
    cudaGetSymbolAddress(&px,  g_x16);
    cudaGetSymbolAddress(&pwg, g_wg16);
    cudaGetSymbolAddress(&pwu, g_wu16);
    cudaGetSymbolAddress(&pwd, g_wd16);
    cudaGetSymbolAddress(&ph,  g_hbuf);

    detect_dtype_k<<<1, 256>>>((const uint32_t*)x);
    const size_t nx = (size_t)NTOK * HD, nw = (size_t)MDIM * HD;

    // try TMA path
    bool tma_ok = false;
    CUtensorMap mXo, mXc, mWgo, mWgc, mWuo, mWuc, mWdo, mWdc, mH;
    tmap_encode_fn enc = get_encode_fn();
    if (enc) {
        CUresult r;
        tma_ok = true;
        r = build_map(enc, &mXo,  x,   HD,   NTOK, 128); tma_ok &= (r == CUDA_SUCCESS);
        r = build_map(enc, &mXc,  px,  HD,   NTOK, 128); tma_ok &= (r == CUDA_SUCCESS);
        r = build_map(enc, &mWgo, wg,  HD,   MDIM, 128); tma_ok &= (r == CUDA_SUCCESS);
        r = build_map(enc, &mWgc, pwg, HD,   MDIM, 128); tma_ok &= (r == CUDA_SUCCESS);
        r = build_map(enc, &mWuo, wu,  HD,   MDIM, 128); tma_ok &= (r == CUDA_SUCCESS);
        r = build_map(enc, &mWuc, pwu, HD,   MDIM, 128); tma_ok &= (r == CUDA_SUCCESS);
        r = build_map(enc, &mWdo, wd,  MDIM, HD,   128); tma_ok &= (r == CUDA_SUCCESS);
        r = build_map(enc, &mWdc, pwd, MDIM, HD,   128); tma_ok &= (r == CUDA_SUCCESS);
        r = build_map(enc, &mH,   ph,  MDIM, NTOK, 256); tma_ok &= (r == CUDA_SUCCESS);
    }

    if (tma_ok) {
        // conditional conversions: x/wg/wu only if fp32 (1 launch); wd if not fp16
        convert3_to_half_k<<<(int)(nw / 2048), 256>>>(x, (__half*)px, nx,
                                                      wg, (__half*)pwg,
                                                      wu, (__half*)pwu, nw, 2);
        convert_to_half_k<<<(int)(nw / 2048), 256>>>(wd, (__half*)pwd, nw, 1);

        constexpr int SMEM1 = 2048 + 4 * 48 * 1024;
        constexpr int SMEM2 = 2048 + 4 * 48 * 1024;
        cudaFuncSetAttribute((const void*)mlp_gemm_tma<128, 4, true, 64, 4>,
                             cudaFuncAttributeMaxDynamicSharedMemorySize, SMEM1);
        cudaFuncSetAttribute((const void*)mlp_gemm_tma<256, 4, false, 32, 4>,
                             cudaFuncAttributeMaxDynamicSharedMemorySize, SMEM2);

        mlp_gemm_tma<128, 4, true, 64, 4><<<dim3(NTOK / 128, MDIM / 128), 544, SMEM1>>>(
            mXo, mXc, mWgo, mWgc, mWuo, mWuc, ph);
        mlp_gemm_tma<256, 4, false, 32, 4><<<dim3(NTOK / 256, HD / 128), 544, SMEM2>>>(
            mH, mH, mWdo, mWdc, mWdo, mWdc, d_out);
    } else {
        // fallback: full conversion + proven cp.async kernels
        convert3_to_half_k<<<(int)(nw / 2048), 256>>>(x, (__half*)px, nx,
                                                      wg, (__half*)pwg,
                                                      wu, (__half*)pwu, nw, 0);
        convert_to_half_k<<<(int)(nw / 2048), 256>>>(wd, (__half*)pwd, nw, 0);

        constexpr int SMEM1 = 4 * (3 * 128 * 128) + 256;
        constexpr int SMEM2 = 5 * (2 * 128 * 128) + 256;
        cudaFuncSetAttribute((const void*)mlp_gemm_cp<16, 4, true>,
                             cudaFuncAttributeMaxDynamicSharedMemorySize, SMEM1);
        cudaFuncSetAttribute((const void*)mlp_gemm_cp<8, 5, false>,
                             cudaFuncAttributeMaxDynamicSharedMemorySize, SMEM2);

        mlp_gemm_cp<16, 4, true><<<dim3(NTOK / 128, MDIM / 128), 512, SMEM1>>>(
            (__half*)px, (__half*)pwg, (__half*)pwu, ph);
        mlp_gemm_cp<8, 5, false><<<dim3(NTOK / 128, HD / 128), 256, SMEM2>>>(
            (__half*)ph, (__half*)pwd, (__half*)pwd, d_out);
    }
}

// round 16
// speedup vs baseline: 1.0146x; 1.0118x over previous
#include <cuda_runtime.h>
#include <cuda_fp16.h>
#include <cuda_bf16.h>
#include <cuda.h>
#include <cstdint>

// ---------------- problem dims ----------------
static constexpr int HD   = 4096;
static constexpr int MDIM = 14336;
static constexpr int NTOK = 8192;   // 4 * 2048 tokens

// fp16 scratch (used only when needed) + intermediate h (always fp16)
__device__ __align__(1024) __half g_x16[(size_t)NTOK * HD];
__device__ __align__(1024) __half g_wg16[(size_t)MDIM * HD];
__device__ __align__(1024) __half g_wu16[(size_t)MDIM * HD];
__device__ __align__(1024) __half g_wd16[(size_t)HD * MDIM];
__device__ __align__(1024) __half g_hbuf[(size_t)NTOK * MDIM];
__device__ int g_dtype;   // 0 = fp16, 1 = bf16, 2 = fp32

// ---------------- dtype detector ----------------
__device__ __forceinline__ bool plaus_f(float v) {
    return isfinite(v) && fabsf(v) > 1e-4f && fabsf(v) < 100.0f;
}
__device__ __forceinline__ float h_bits(uint32_t b) {
    __half_raw r; r.x = (unsigned short)b;
    return __half2float(*reinterpret_cast<__half*>(&r));
}
__global__ void detect_dtype_k(const uint32_t* __restrict__ w) {
    __shared__ int c[3];
    if (threadIdx.x < 3) c[threadIdx.x] = 0;
    __syncthreads();
    int c16 = 0, cb = 0, c32 = 0;
    for (int i = threadIdx.x; i < 8192; i += 256) {
        uint32_t v = w[i];
        if (plaus_f(__uint_as_float(v))) c32++;
        uint32_t lo = v & 0xFFFFu, hi = v >> 16;
        if (plaus_f(h_bits(lo)) && plaus_f(h_bits(hi))) c16++;
        if (plaus_f(__uint_as_float(lo << 16)) && plaus_f(__uint_as_float(v & 0xFFFF0000u))) cb++;
    }
    atomicAdd(&c[0], c16); atomicAdd(&c[1], cb); atomicAdd(&c[2], c32);
    __syncthreads();
    if (threadIdx.x == 0) {
        const int thresh = (8192 * 9) / 10;
        int dt;
        if (c[1] > thresh)      dt = 1;
        else if (c[0] > thresh) dt = 0;
        else                    dt = 2;
        g_dtype = dt;
    }
}

// ---------------- conditional conversion -> fp16 ----------------
// mode 0: always convert; mode 2: only if dt==2 (fp32); mode 1: if dt != 0
__device__ __forceinline__ void conv_range(const void* src, __half* dst, size_t n,
                                           int dt, size_t start, size_t stride) {
    for (size_t i = start; i < n; i += stride) {
        uint4 o;
        if (dt == 2) {
            const float4* s = reinterpret_cast<const float4*>((const float*)src + i);
            float4 a = s[0], b = s[1];
            __half2 p0 = __floats2half2_rn(a.x, a.y);
            __half2 p1 = __floats2half2_rn(a.z, a.w);
            __half2 p2 = __floats2half2_rn(b.x, b.y);
            __half2 p3 = __floats2half2_rn(b.z, b.w);
            o = make_uint4(*(uint32_t*)&p0, *(uint32_t*)&p1, *(uint32_t*)&p2, *(uint32_t*)&p3);
        } else if (dt == 1) {
            uint4 s = *reinterpret_cast<const uint4*>((const __nv_bfloat16*)src + i);
            uint32_t ws[4] = {s.x, s.y, s.z, s.w};
            uint32_t po[4];
#pragma unroll
            for (int j = 0; j < 4; j++) {
                float f0 = __uint_as_float(ws[j] << 16);
                float f1 = __uint_as_float(ws[j] & 0xFFFF0000u);
                __half2 p = __floats2half2_rn(f0, f1);
                po[j] = *(uint32_t*)&p;
            }
            o = make_uint4(po[0], po[1], po[2], po[3]);
        } else {
            o = *reinterpret_cast<const uint4*>((const __half*)src + i);
        }
        *reinterpret_cast<uint4*>(dst + i) = o;
    }
}
__global__ void convert_to_half_k(const void* __restrict__ src, __half* __restrict__ dst,
                                  size_t n, int mode) {
    const int dt = g_dtype;
    if (mode == 2 && dt != 2) return;
    if (mode == 1 && dt == 0) return;
    const size_t stride = (size_t)gridDim.x * blockDim.x * 8;
    conv_range(src, dst, n, dt, ((size_t)blockIdx.x * blockDim.x + threadIdx.x) * 8, stride);
}
// x + wg + wu in one launch (all gated by mode semantics of 'mode')
__global__ void convert3_to_half_k(const void* __restrict__ s0, __half* __restrict__ d0, size_t n0,
                                   const void* __restrict__ s1, __half* __restrict__ d1,
                                   const void* __restrict__ s2, __half* __restrict__ d2, size_t n12,
                                   int mode) {
    const int dt = g_dtype;
    if (mode == 2 && dt != 2) return;
    if (mode == 1 && dt == 0) return;
    const size_t stride = (size_t)gridDim.x * blockDim.x * 8;
    const size_t start = ((size_t)blockIdx.x * blockDim.x + threadIdx.x) * 8;
    conv_range(s0, d0, n0,  dt, start, stride);
    conv_range(s1, d1, n12, dt, start, stride);
    conv_range(s2, d2, n12, dt, start, stride);
}

// ---------------- asm helpers ----------------
__device__ __forceinline__ uint32_t smem_u32(const void* p) {
    uint32_t a;
    asm("{ .reg .u64 t; cvta.to.shared.u64 t, %1; cvt.u32.u64 %0, t; }" : "=r"(a) : "l"(p));
    return a;
}

#define CP_ASYNC16(smem_addr, gptr) \
    asm volatile("cp.async.cg.shared.global [%0], [%1], 16;" \
                 :: "r"(smem_addr), "l"(gptr) : "memory")
#define CP_COMMIT() asm volatile("cp.async.commit_group;" ::: "memory")
#define CP_WAIT(n)  asm volatile("cp.async.wait_group %0;" :: "n"(n) : "memory")
#define CP_WAIT_ALL() asm volatile("cp.async.wait_all;" ::: "memory")

#define MBARRIER_INIT(addr, cnt) \
    asm volatile("mbarrier.init.shared.b64 [%0], %1;" :: "r"((uint32_t)(addr)), "r"((uint32_t)(cnt)) : "memory")
#define MBARRIER_ARRIVE(addr) \
    asm volatile("mbarrier.arrive.shared.b64 _, [%0];" :: "r"((uint32_t)(addr)) : "memory")
#define MBARRIER_EXPECT_TX(addr, bytes) \
    asm volatile("mbarrier.arrive.expect_tx.shared.b64 _, [%0], %1;" :: "r"((uint32_t)(addr)), "r"((uint32_t)(bytes)) : "memory")

#define MBARRIER_WAIT_PARITY(mbar_smem_addr, phase_parity) do { \
    uint32_t _mbar = (uint32_t)(mbar_smem_addr); \
    uint32_t _parity = (uint32_t)(phase_parity); \
    uint32_t _done; \
    asm volatile( \
        "{\n\t.reg .pred p;\n\t" \
        "mbarrier.try_wait.parity.shared.b64 p, [%1], %2;\n\t" \
        "selp.b32 %0, 1, 0, p;\n\t}" \
        : "=r"(_done) : "r"(_mbar), "r"(_parity) : "memory"); \
    if (!_done) { \
        asm volatile( \
            "{\n\t.reg .pred P1;\n\t" \
            "WAIT_LOOP_%=:\n\t" \
            "mbarrier.try_wait.parity.shared.b64 P1, [%0], %1, 0x989680;\n\t" \
            "@P1 bra.uni WAIT_DONE_%=;\n\t" \
            "bra.uni WAIT_LOOP_%=;\n\t" \
            "WAIT_DONE_%=:\n\t}" \
            :: "r"(_mbar), "r"(_parity) : "memory"); \
    } \
} while(0)

#define FENCE_PROXY_ASYNC() \
    asm volatile("fence.proxy.async.shared::cta;" ::: "memory")

__device__ __forceinline__ void tma_load_2d(uint32_t smem_addr, const void* tmap,
                                            int32_t cx, int32_t cy, uint32_t mbar) {
    asm volatile(
        "cp.async.bulk.tensor.2d.shared::cta.global.tile.mbarrier::complete_tx::bytes "
        "[%0], [%1, {%2, %3}], [%4];"
        :: "r"(smem_addr), "l"(tmap), "r"(cx), "r"(cy), "r"(mbar) : "memory");
}

__device__ __forceinline__ void ldsm_x4(uint32_t& r0, uint32_t& r1, uint32_t& r2, uint32_t& r3,
                                        uint32_t addr) {
    asm volatile("ldmatrix.sync.aligned.m8n8.x4.shared.b16 {%0,%1,%2,%3}, [%4];"
                 : "=r"(r0), "=r"(r1), "=r"(r2), "=r"(r3) : "r"(addr));
}

template<bool BF16>
__device__ __forceinline__ void mma_any(float* c, const uint32_t* a, const uint32_t* b) {
    if (BF16)
        asm volatile(
            "mma.sync.aligned.m16n8k16.row.col.f32.bf16.bf16.f32 "
            "{%0,%1,%2,%3}, {%4,%5,%6,%7}, {%8,%9}, {%0,%1,%2,%3};"
            : "+f"(c[0]), "+f"(c[1]), "+f"(c[2]), "+f"(c[3])
            : "r"(a[0]), "r"(a[1]), "r"(a[2]), "r"(a[3]), "r"(b[0]), "r"(b[1]));
    else
        asm volatile(
            "mma.sync.aligned.m16n8k16.row.col.f32.f16.f16.f32 "
            "{%0,%1,%2,%3}, {%4,%5,%6,%7}, {%8,%9}, {%0,%1,%2,%3};"
            : "+f"(c[0]), "+f"(c[1]), "+f"(c[2]), "+f"(c[3])
            : "r"(a[0]), "r"(a[1]), "r"(a[2]), "r"(a[3]), "r"(b[0]), "r"(b[1]));
}

__device__ __forceinline__ void store_out_dtype(void* outv, size_t i0, size_t i1,
                                                const float* a4, int dt) {
    if (dt == 2) {
        *reinterpret_cast<float2*>((float*)outv + i0) = make_float2(a4[0], a4[1]);
        *reinterpret_cast<float2*>((float*)outv + i1) = make_float2(a4[2], a4[3]);
    } else if (dt == 1) {
        __nv_bfloat162 b0 = __floats2bfloat162_rn(a4[0], a4[1]);
        __nv_bfloat162 b1 = __floats2bfloat162_rn(a4[2], a4[3]);
        *reinterpret_cast<__nv_bfloat162*>((__nv_bfloat16*)outv + i0) = b0;
        *reinterpret_cast<__nv_bfloat162*>((__nv_bfloat16*)outv + i1) = b1;
    } else {
        *reinterpret_cast<__half2*>((__half*)outv + i0) = __floats2half2_rn(a4[0], a4[1]);
        *reinterpret_cast<__half2*>((__half*)outv + i1) = __floats2half2_rn(a4[2], a4[3]);
    }
}

// consumer mainloop with A-fragment double buffering: prefetch ks+1's A LDSMs
// during ks's MMAs. Math order identical to the proven loop (same MMA sequence).
// Register budget: acc 64 + aF 32 + bF 8 + addressing ~12 <= 120-reg cap @544thr.
template<bool BF16, int KITERS, int NSTAGES>
__device__ __forceinline__ void consumer_loop(
    uint32_t sb, uint32_t off_full, uint32_t off_empty, uint32_t off_tile,
    uint32_t stage_bytes, uint32_t boff,
    uint32_t a_row, uint32_t a_koff, uint32_t b_row, uint32_t b_koff, uint32_t xor7,
    int lane, float (&acc)[4][4][4])
{
    int s = 0, ph = 0;
    for (int k = 0; k < KITERS; k++) {
        MBARRIER_WAIT_PARITY(sb + off_full + s * 8, ph);
        const uint32_t stA = sb + off_tile + (uint32_t)s * stage_bytes;
        const uint32_t stB = stA + boff;

        uint32_t aF[2][4][4];
        // preload ks=0 A fragments
        {
            const uint32_t kbA0 = a_koff ^ xor7;
#pragma unroll
            for (int mb = 0; mb < 4; mb++)
                ldsm_x4(aF[0][mb][0], aF[0][mb][1], aF[0][mb][2], aF[0][mb][3],
                        stA + (a_row + mb * 16) * 128 + kbA0);
        }
#pragma unroll
        for (int ks = 0; ks < 4; ks++) {
            const int cur = ks & 1;
            const uint32_t kbB = ((uint32_t)(ks * 32) + b_koff) ^ xor7;
            uint32_t bF[2][4];
#pragma unroll
            for (int nb = 0; nb < 2; nb++)
                ldsm_x4(bF[nb][0], bF[nb][1], bF[nb][2], bF[nb][3],
                        stB + (b_row + nb * 16) * 128 + kbB);
            if (ks < 3) {
                // prefetch next ks's A fragments; overlaps with this ks's MMAs
                const uint32_t kbA = ((uint32_t)((ks + 1) * 32) + a_koff) ^ xor7;
#pragma unroll
                for (int mb = 0; mb < 4; mb++)
                    ldsm_x4(aF[cur ^ 1][mb][0], aF[cur ^ 1][mb][1],
                            aF[cur ^ 1][mb][2], aF[cur ^ 1][mb][3],
                            stA + (a_row + mb * 16) * 128 + kbA);
            }
#pragma unroll
            for (int mb = 0; mb < 4; mb++)
#pragma unroll
                for (int ns = 0; ns < 4; ns++)
                    mma_any<BF16>(acc[mb][ns], aF[cur][mb], &bF[ns >> 1][(ns & 1) * 2]);
        }
        if (lane == 0) MBARRIER_ARRIVE(sb + off_empty + s * 8);
        if (++s == NSTAGES) { s = 0; ph ^= 1; }
    }
}

// =======================================================================
// TMA GEMM (proven config: 16 compute warps 64x32 + producer = 544 thr).
// FUSED  (MTILE=128): warps 0-7 gate, 8-15 up, shared A; silu-combine -> fp16 h.
//        Epilogue 'up' exchange packed as half2 (32 KB).
// !FUSED (MTILE=256): 4x4 warp grid; store in detected dtype.
// =======================================================================
template<int MTILE, int NSTAGES, bool FUSED, int NTM, int GRP>
__global__ void __launch_bounds__(544, 1)
mlp_gemm_tma(const __grid_constant__ CUtensorMap mapAo,
             const __grid_constant__ CUtensorMap mapAc,
             const __grid_constant__ CUtensorMap mapB0o,
             const __grid_constant__ CUtensorMap mapB0c,
             const __grid_constant__ CUtensorMap mapB1o,
             const __grid_constant__ CUtensorMap mapB1c,
             void* __restrict__ outv)
{
    constexpr int KDIM       = FUSED ? HD : MDIM;
    constexpr int KITERS     = KDIM / 64;
    constexpr int OUT_STRIDE = FUSED ? MDIM : HD;
    constexpr uint32_t ATILE = (uint32_t)MTILE * 128;
    constexpr uint32_t BTILE = 128 * 128;
    constexpr uint32_t STAGE = ATILE + (FUSED ? 2 : 1) * BTILE;

    extern __shared__ char smem_raw[];
    const uint32_t raw = smem_u32(smem_raw);
    const uint32_t sb  = (raw + 1023u) & ~1023u;

    const int tid  = threadIdx.x;
    const int wid  = tid >> 5;
    const int lane = tid & 31;
    const int dt   = g_dtype;

    const uint32_t OFF_FULL  = 0;
    const uint32_t OFF_EMPTY = 256;
    const uint32_t OFF_TILE  = 1024;

    if (tid == 0) {
        for (int s = 0; s < NSTAGES; s++) {
            MBARRIER_INIT(sb + OFF_FULL  + s * 8, 1);
            MBARRIER_INIT(sb + OFF_EMPTY + s * 8, 16);
        }
        FENCE_PROXY_ASYNC();
    }
    __syncthreads();

    // swizzled rasterization: groups of GRP N-tiles x all NTM M-tiles
    const int id = blockIdx.y * gridDim.x + blockIdx.x;
    const int gper = NTM * GRP;
    const int grp = id / gper;
    const int rem = id % gper;
    const int m0 = (rem % NTM) * MTILE;
    const int n0 = (grp * GRP + rem / NTM) * 128;

    // map selection (uniform): A conv only for fp32; B conv for fp32 (FUSED) or dt!=0 (!FUSED)
    const void* pA  = (FUSED && dt == 2) ? (const void*)&mapAc  : (const void*)&mapAo;
    const bool bconv = FUSED ? (dt == 2) : (dt != 0);
    const void* pB0 = bconv ? (const void*)&mapB0c : (const void*)&mapB0o;
    const void* pB1 = bconv ? (const void*)&mapB1c : (const void*)&mapB1o;

    if (wid == 16) {
        // ---------------- TMA producer ----------------
        if (lane == 0) {
            int s = 0, ph = 1;
            for (int k = 0; k < KITERS; k++) {
                MBARRIER_WAIT_PARITY(sb + OFF_EMPTY + s * 8, ph);
                MBARRIER_EXPECT_TX(sb + OFF_FULL + s * 8, STAGE);
                const uint32_t st = sb + OFF_TILE + (uint32_t)s * STAGE;
                tma_load_2d(st,         pA,  k * 64, m0, sb + OFF_FULL + s * 8);
                tma_load_2d(st + ATILE, pB0, k * 64, n0, sb + OFF_FULL + s * 8);
                if (FUSED)
                    tma_load_2d(st + ATILE + BTILE, pB1, k * 64, n0, sb + OFF_FULL + s * 8);
                if (++s == NSTAGES) { s = 0; ph ^= 1; }
            }
        }
    } else {
        // ---------------- compute warps (64x32 tiles, proven layout) ----------------
        const int  cq    = FUSED ? (wid & 7) : wid;
        const bool is_up = FUSED && (wid >= 8);
        const int  wm0   = FUSED ? (cq & 1) * 64 : (cq & 3) * 64;
        const int  wn0   = FUSED ? (cq >> 1) * 32 : (cq >> 2) * 32;

        const uint32_t xor7   = (uint32_t)(lane & 7) << 4;
        const uint32_t a_row  = (uint32_t)(wm0 + (lane & 15));
        const uint32_t a_koff = (uint32_t)(lane & 16);
        const uint32_t b_row  = (uint32_t)(wn0 + (lane & 7) + ((lane & 16) >> 1));
        const uint32_t b_koff = (uint32_t)((lane & 8) << 1);
        const uint32_t boff   = ATILE + (is_up ? BTILE : 0);

        float acc[4][4][4];
#pragma unroll
        for (int i = 0; i < 4; i++)
#pragma unroll
            for (int j = 0; j < 4; j++)
#pragma unroll
                for (int v = 0; v < 4; v++) acc[i][j][v] = 0.0f;

        if (FUSED && dt == 1)
            consumer_loop<true,  KITERS, NSTAGES>(sb, OFF_FULL, OFF_EMPTY, OFF_TILE, STAGE,
                                                  boff, a_row, a_koff, b_row, b_koff, xor7,
                                                  lane, acc);
        else
            consumer_loop<false, KITERS, NSTAGES>(sb, OFF_FULL, OFF_EMPTY, OFF_TILE, STAGE,
                                                  boff, a_row, a_koff, b_row, b_koff, xor7,
                                                  lane, acc);

        const int g = lane >> 2, c2 = (lane & 3) * 2;

        if (!FUSED) {
#pragma unroll
            for (int mb = 0; mb < 4; mb++)
#pragma unroll
                for (int ns = 0; ns < 4; ns++) {
                    const int mrow = m0 + wm0 + mb * 16 + g;
                    const int ncol = n0 + wn0 + ns * 8 + c2;
                    store_out_dtype(outv, (size_t)mrow * OUT_STRIDE + ncol,
                                    (size_t)(mrow + 8) * OUT_STRIDE + ncol,
                                    acc[mb][ns], dt);
                }
            return;
        }

        // fused epilogue: exchange 'up' via SMEM as packed half2, silu-combine
        __syncthreads();   // (1)
        uint32_t* exch = reinterpret_cast<uint32_t*>(smem_raw + (sb - raw) + OFF_TILE);
        __half* out = reinterpret_cast<__half*>(outv);
        if (is_up) {
            const int t = (wid - 8) * 32 + lane;   // 0..255
#pragma unroll
            for (int mb = 0; mb < 4; mb++)
#pragma unroll
                for (int ns = 0; ns < 4; ns++) {
                    __half2 p0 = __floats2half2_rn(acc[mb][ns][0], acc[mb][ns][1]);
                    __half2 p1 = __floats2half2_rn(acc[mb][ns][2], acc[mb][ns][3]);
                    exch[((mb * 4 + ns) * 2 + 0) * 256 + t] = *reinterpret_cast<uint32_t*>(&p0);
                    exch[((mb * 4 + ns) * 2 + 1) * 256 + t] = *reinterpret_cast<uint32_t*>(&p1);
                }
        }
        __syncthreads();   // (2)
        if (!is_up) {
            const int t = wid * 32 + lane;
#pragma unroll
            for (int mb = 0; mb < 4; mb++)
#pragma unroll
                for (int ns = 0; ns < 4; ns++) {
                    uint32_t u0 = exch[((mb * 4 + ns) * 2 + 0) * 256 + t];
                    uint32_t u1 = exch[((mb * 4 + ns) * 2 + 1) * 256 + t];
                    const float2 up01 = __half22float2(*reinterpret_cast<__half2*>(&u0));
                    const float2 up23 = __half22float2(*reinterpret_cast<__half2*>(&u1));
                    const float upv[4] = {up01.x, up01.y, up23.x, up23.y};
                    float r[4];
#pragma unroll
                    for (int v = 0; v < 4; v++) {
                        const float gt = acc[mb][ns][v];
                        r[v] = upv[v] * (gt / (1.0f + __expf(-gt)));
                    }
                    const int mrow = m0 + wm0 + mb * 16 + g;
                    const int ncol = n0 + wn0 + ns * 8 + c2;
                    *reinterpret_cast<__half2*>(out + (size_t)mrow * OUT_STRIDE + ncol) =
                        __floats2half2_rn(r[0], r[1]);
                    *reinterpret_cast<__half2*>(out + (size_t)(mrow + 8) * OUT_STRIDE + ncol) =
                        __floats2half2_rn(r[2], r[3]);
                }
        }
        return;
    }

    if (FUSED) { __syncthreads(); __syncthreads(); }
}

// =======================================================================
// Fallback: cp.async GEMM (proven R4) — only if tensormap creation fails
// =======================================================================
template<int NTHREADS>
__device__ __forceinline__ void load_tile(uint32_t smem_tile, const __half* g,
                                          int row0, int kbyte, int ld_elems, int tid) {
    const char* gbase = reinterpret_cast<const char*>(g) + (size_t)row0 * (ld_elems * 2) + kbyte;
#pragma unroll
    for (int c = tid; c < 1024; c += NTHREADS) {
        const int row = c >> 3;
        const int col = (c & 7) << 4;
        const char* src = gbase + (size_t)row * (ld_elems * 2) + col;
        const uint32_t dst = smem_tile + row * 128 + (col ^ ((row & 7) << 4));
        CP_ASYNC16(dst, src);
    }
}

template<int NW, int NSTAGES, bool FUSED>
__global__ void __launch_bounds__(NW * 32, 1)
mlp_gemm_cp(const __half* __restrict__ A, const __half* __restrict__ B0,
            const __half* __restrict__ B1, void* __restrict__ outv)
{
    constexpr int NTH        = NW * 32;
    constexpr int KDIM       = FUSED ? HD : MDIM;
    constexpr int KITERS     = KDIM / 64;
    constexpr int OUT_STRIDE = FUSED ? MDIM : HD;
    constexpr uint32_t ATILE = 128 * 128;
    constexpr uint32_t STAGE = FUSED ? 3 * ATILE : 2 * ATILE;

    extern __shared__ char smem_raw[];
    const uint32_t raw = smem_u32(smem_raw);
    const uint32_t sb  = (raw + 127u) & ~127u;

    const int tid  = threadIdx.x;
    const int wid  = tid >> 5;
    const int lane = tid & 31;

    const int m0 = blockIdx.x * 128;
    const int n0 = blockIdx.y * 128;

    const int  cq    = FUSED ? (wid & 7) : wid;
    const bool is_up = FUSED && (wid >= 8);
    const int  wm0   = (cq & 1) * 64;
    const int  wn0   = (cq >> 1) * 32;

    const uint32_t xor7   = (uint32_t)(lane & 7) << 4;
    const uint32_t a_row  = (uint32_t)(wm0 + (lane & 15));
    const uint32_t a_koff = (uint32_t)(lane & 16);
    const uint32_t b_row  = (uint32_t)(wn0 + (lane & 7) + ((lane & 16) >> 1));
    const uint32_t b_koff = (uint32_t)((lane & 8) << 1);
    const uint32_t boff   = is_up ? 2 * ATILE : ATILE;

    float acc[4][4][4];
#pragma unroll
    for (int i = 0; i < 4; i++)
#pragma unroll
        for (int j = 0; j < 4; j++)
#pragma unroll
            for (int v = 0; v < 4; v++) acc[i][j][v] = 0.0f;

    auto load_stage = [&](int s, int k) {
        const uint32_t st = sb + (uint32_t)s * STAGE;
        const int kb = k * 128;
        load_tile<NTH>(st,         A,  m0, kb, KDIM, tid);
        load_tile<NTH>(st + ATILE, B0, n0, kb, KDIM, tid);
        if (FUSED)
            load_tile<NTH>(st + 2 * ATILE, B1, n0, kb, KDIM, tid);
    };

#pragma unroll
    for (int s = 0; s < NSTAGES - 1; s++) { load_stage(s, s); CP_COMMIT(); }

    int sc = 0;
    for (int k = 0; k < KITERS; k++) {
        CP_WAIT(NSTAGES - 2);
        __syncthreads();
        const uint32_t stA = sb + (uint32_t)sc * STAGE;
        const uint32_t stB = stA + boff;
#pragma unroll
        for (int ks = 0; ks < 4; ks++) {
            const uint32_t kbA = ((uint32_t)(ks * 32) + a_koff) ^ xor7;
            const uint32_t kbB = ((uint32_t)(ks * 32) + b_koff) ^ xor7;
            uint32_t aF[4][4];
#pragma unroll
            for (int mb = 0; mb < 4; mb++)
                ldsm_x4(aF[mb][0], aF[mb][1], aF[mb][2], aF[mb][3],
                        stA + (a_row + mb * 16) * 128 + kbA);
            uint32_t bF[2][4];
#pragma unroll
            for (int nb = 0; nb < 2; nb++)
                ldsm_x4(bF[nb][0], bF[nb][1], bF[nb][2], bF[nb][3],
                        stB + (b_row + nb * 16) * 128 + kbB);
#pragma unroll
            for (int mb = 0; mb < 4; mb++)
#pragma unroll
                for (int ns = 0; ns < 4; ns++)
                    mma_any<false>(acc[mb][ns], aF[mb], &bF[ns >> 1][(ns & 1) * 2]);
        }
        __syncthreads();
        const int kn = k + NSTAGES - 1;
        if (kn < KITERS) load_stage((sc + NSTAGES - 1) % NSTAGES, kn);
        CP_COMMIT();
        sc = (sc + 1 == NSTAGES) ? 0 : sc + 1;
    }

    const int g = lane >> 2, c2 = (lane & 3) * 2;

    if (!FUSED) {
        const int dt = g_dtype;
#pragma unroll
        for (int mb = 0; mb < 4; mb++)
#pragma unroll
            for (int ns = 0; ns < 4; ns++) {
                const int mrow = m0 + wm0 + mb * 16 + g;
                const int ncol = n0 + wn0 + ns * 8 + c2;
                store_out_dtype(outv, (size_t)mrow * OUT_STRIDE + ncol,
                                (size_t)(mrow + 8) * OUT_STRIDE + ncol, acc[mb][ns], dt);
            }
        return;
    }

    CP_WAIT_ALL();
    __syncthreads();
    float* exch = reinterpret_cast<float*>(smem_raw + (sb - raw));
    __half* out = reinterpret_cast<__half*>(outv);
    if (is_up) {
        const int t = (wid - 8) * 32 + lane;
#pragma unroll
        for (int mb = 0; mb < 4; mb++)
#pragma unroll
            for (int ns = 0; ns < 4; ns++)
#pragma unroll
                for (int v = 0; v < 4; v++)
                    exch[((mb * 4 + ns) * 4 + v) * 256 + t] = acc[mb][ns][v];
    }
    __syncthreads();
    if (!is_up) {
        const int t = wid * 32 + lane;
#pragma unroll
        for (int mb = 0; mb < 4; mb++)
#pragma unroll
            for (int ns = 0; ns < 4; ns++) {
                float r[4];
#pragma unroll
                for (int v = 0; v < 4; v++) {
                    const float gt = acc[mb][ns][v];
                    const float up = exch[((mb * 4 + ns) * 4 + v) * 256 + t];
                    r[v] = up * (gt / (1.0f + __expf(-gt)));
                }
                const int mrow = m0 + wm0 + mb * 16 + g;
                const int ncol = n0 + wn0 + ns * 8 + c2;
                *reinterpret_cast<__half2*>(out + (size_t)mrow * OUT_STRIDE + ncol) =
                    __floats2half2_rn(r[0], r[1]);
                *reinterpret_cast<__half2*>(out + (size_t)(mrow + 8) * OUT_STRIDE + ncol) =
                    __floats2half2_rn(r[2], r[3]);
            }
    }
}

// ---------------- host side ----------------
typedef CUresult (*tmap_encode_fn)(
    CUtensorMap*, CUtensorMapDataType, cuuint32_t, void*,
    const cuuint64_t*, const cuuint64_t*, const cuuint32_t*, const cuuint32_t*,
    CUtensorMapInterleave, CUtensorMapSwizzle, CUtensorMapL2promotion, CUtensorMapFloatOOBfill);

static tmap_encode_fn get_encode_fn() {
    void* fn = nullptr;
    cudaDriverEntryPointQueryResult st;
    if (cudaGetDriverEntryPointByVersion("cuTensorMapEncodeTiled", &fn, 12000,
                                         cudaEnableDefault, &st) == cudaSuccess && fn)
        return (tmap_encode_fn)fn;
    fn = nullptr;
    if (cudaGetDriverEntryPointByVersion("cuTensorMapEncodeTiled", &fn, 13000,
                                         cudaEnableDefault, &st) == cudaSuccess && fn)
        return (tmap_encode_fn)fn;
    return nullptr;
}

static CUresult build_map(tmap_encode_fn enc, CUtensorMap* m, const void* base,
                          uint64_t inner, uint64_t outer, uint32_t box_rows) {
    cuuint64_t dims[2]    = {inner, outer};
    cuuint64_t strides[1] = {inner * 2};
    cuuint32_t box[2]     = {64u, box_rows};
    cuuint32_t es[2]      = {1u, 1u};
    return enc(m, CU_TENSOR_MAP_DATA_TYPE_FLOAT16, 2, const_cast<void*>(base),
               dims, strides, box, es,
               CU_TENSOR_MAP_INTERLEAVE_NONE, CU_TENSOR_MAP_SWIZZLE_128B,
               CU_TENSOR_MAP_L2_PROMOTION_L2_128B, CU_TENSOR_MAP_FLOAT_OOB_FILL_NONE);
}

extern "C" void kernel_launch(void* const* d_in, const int* in_sizes, int n_in,
                              void* d_out, int out_size) {
    (void)in_sizes; (void)n_in; (void)out_size;

    const void* x  = d_in[0];
    const void* wg = d_in[1];
    const void* wu = d_in[2];
    const void* wd = d_in[3];

    void *px, *pwg, *pwu, *pwd, *ph;
    cudaGetSymbolAddress(&px,  g_x16);
    cudaGetSymbolAddress(&pwg, g_wg16);
    cudaGetSymbolAddress(&pwu, g_wu16);
    cudaGetSymbolAddress(&pwd, g_wd16);
    cudaGetSymbolAddress(&ph,  g_hbuf);

    detect_dtype_k<<<1, 256>>>((const uint32_t*)x);
    const size_t nx = (size_t)NTOK * HD, nw = (size_t)MDIM * HD;

    // try TMA path
    bool tma_ok = false;
    CUtensorMap mXo, mXc, mWgo, mWgc, mWuo, mWuc, mWdo, mWdc, mH;
    tmap_encode_fn enc = get_encode_fn();
    if (enc) {
        CUresult r;
        tma_ok = true;
        r = build_map(enc, &mXo,  x,   HD,   NTOK, 128); tma_ok &= (r == CUDA_SUCCESS);
        r = build_map(enc, &mXc,  px,  HD,   NTOK, 128); tma_ok &= (r == CUDA_SUCCESS);
        r = build_map(enc, &mWgo, wg,  HD,   MDIM, 128); tma_ok &= (r == CUDA_SUCCESS);
        r = build_map(enc, &mWgc, pwg, HD,   MDIM, 128); tma_ok &= (r == CUDA_SUCCESS);
        r = build_map(enc, &mWuo, wu,  HD,   MDIM, 128); tma_ok &= (r == CUDA_SUCCESS);
        r = build_map(enc, &mWuc, pwu, HD,   MDIM, 128); tma_ok &= (r == CUDA_SUCCESS);
        r = build_map(enc, &mWdo, wd,  MDIM, HD,   128); tma_ok &= (r == CUDA_SUCCESS);
        r = build_map(enc, &mWdc, pwd, MDIM, HD,   128); tma_ok &= (r == CUDA_SUCCESS);
        r = build_map(enc, &mH,   ph,  MDIM, NTOK, 256); tma_ok &= (r == CUDA_SUCCESS);
    }

    if (tma_ok) {
        // conditional conversions: x/wg/wu only if fp32 (1 launch); wd if not fp16
        convert3_to_half_k<<<(int)(nw / 2048), 256>>>(x, (__half*)px, nx,
                                                      wg, (__half*)pwg,
                                                      wu, (__half*)pwu, nw, 2);
        convert_to_half_k<<<(int)(nw / 2048), 256>>>(wd, (__half*)pwd, nw, 1);

        constexpr int SMEM1 = 2048 + 4 * 48 * 1024;
        constexpr int SMEM2 = 2048 + 4 * 48 * 1024;
        cudaFuncSetAttribute((const void*)mlp_gemm_tma<128, 4, true, 64, 4>,
                             cudaFuncAttributeMaxDynamicSharedMemorySize, SMEM1);
        cudaFuncSetAttribute((const void*)mlp_gemm_tma<256, 4, false, 32, 4>,
                             cudaFuncAttributeMaxDynamicSharedMemorySize, SMEM2);

        mlp_gemm_tma<128, 4, true, 64, 4><<<dim3(NTOK / 128, MDIM / 128), 544, SMEM1>>>(
            mXo, mXc, mWgo, mWgc, mWuo, mWuc, ph);
        mlp_gemm_tma<256, 4, false, 32, 4><<<dim3(NTOK / 256, HD / 128), 544, SMEM2>>>(
            mH, mH, mWdo, mWdc, mWdo, mWdc, d_out);
    } else {
        // fallback: full conversion + proven cp.async kernels
        convert3_to_half_k<<<(int)(nw / 2048), 256>>>(x, (__half*)px, nx,
                                                      wg, (__half*)pwg,
                                                      wu, (__half*)pwu, nw, 0);
        convert_to_half_k<<<(int)(nw / 2048), 256>>>(wd, (__half*)pwd, nw, 0);

        constexpr int SMEM1 = 4 * (3 * 128 * 128) + 256;
        constexpr int SMEM2 = 5 * (2 * 128 * 128) + 256;
        cudaFuncSetAttribute((const void*)mlp_gemm_cp<16, 4, true>,
                             cudaFuncAttributeMaxDynamicSharedMemorySize, SMEM1);
        cudaFuncSetAttribute((const void*)mlp_gemm_cp<8, 5, false>,
                             cudaFuncAttributeMaxDynamicSharedMemorySize, SMEM2);

        mlp_gemm_cp<16, 4, true><<<dim3(NTOK / 128, MDIM / 128), 512, SMEM1>>>(
            (__half*)px, (__half*)pwg, (__half*)pwu, ph);
        mlp_gemm_cp<8, 5, false><<<dim3(NTOK / 128, HD / 128), 256, SMEM2>>>(
            (__half*)ph, (__half*)pwd, (__half*)pwd, d_out);
    }
}